// round 11
// baseline (speedup 1.0000x reference)
#include <cuda_runtime.h>
#include <cuda_fp16.h>
#include <cstdint>

// Problem dims (fixed):
//  x: (2,1024,32,512) -> M = 65536 rows of K=512
//  QKV cols = 1536 (Q 0-511, K 512-1023, V 1024-1535), out proj N=512
#define M_TOTAL 65536

// ---------------- scratch (device globals; no runtime allocation) ----------
__device__ uint32_t g_Qh[(size_t)M_TOTAL * 256];    // roped+scaled Q, half2 along d
__device__ uint32_t g_Kh[(size_t)M_TOTAL * 256];    // roped K, half2 along d
__device__ uint32_t g_Vh[(size_t)M_TOTAL * 256];    // V, half2 along d
__device__ uint32_t g_Xp[(size_t)M_TOTAL * 256];    // x as half2 pairs along k
__device__ uint32_t g_AOp[(size_t)M_TOTAL * 256];   // attn out as half2 pairs
__device__ uint32_t g_WQKVp[256 * 1536];            // [k2][n] half2(w[2k2][n], w[2k2+1][n])
__device__ uint32_t g_WOp[256 * 512];
__device__ float    g_cos[1024];
__device__ float    g_sin[1024];
__device__ int      g_mask[2];

// ---------------- helpers ----------------------------------------------------
__device__ __forceinline__ uint32_t packh2(float lo, float hi) {
    __half2 h = __floats2half2_rn(lo, hi);
    return *reinterpret_cast<uint32_t*>(&h);
}
__device__ __forceinline__ float2 unpackh2(uint32_t w) {
    return __half22float2(*reinterpret_cast<__half2*>(&w));
}
__device__ __forceinline__ uint32_t smem_u32(const void* p) {
    uint32_t a;
    asm("{ .reg .u64 t; cvta.to.shared.u64 t, %1; cvt.u32.u64 %0, t; }"
        : "=r"(a) : "l"(p));
    return a;
}
__device__ __forceinline__ void cp16(uint32_t dst, const void* src) {
    asm volatile("cp.async.cg.shared.global [%0], [%1], 16;"
                 :: "r"(dst), "l"(src) : "memory");
}
__device__ __forceinline__ void cp_commit() {
    asm volatile("cp.async.commit_group;" ::: "memory");
}

// ---------------- setup: pack x/weights to fp16, rope table, mask -----------
__global__ void setup_kernel(
    const float* __restrict__ x,
    const float* __restrict__ w_q,
    const float* __restrict__ w_kv,
    const float* __restrict__ w_out,
    const float* __restrict__ inv_freq,
    const uint32_t* __restrict__ m)
{
    const int bid = blockIdx.x;
    if (bid < 16384) {
        size_t base = ((size_t)bid * 256 + threadIdx.x) * 4;
#pragma unroll
        for (int j = 0; j < 4; j++) {
            size_t w = base + j;
            float2 v = *(const float2*)(x + 2 * w);
            g_Xp[w] = packh2(v.x, v.y);
        }
    } else if (bid < 16384 + 512) {
        // weights, k-pair packed: qkv 256x1536 words, out 256x512 words
        size_t base = ((size_t)(bid - 16384) * 256 + threadIdx.x) * 4;
#pragma unroll
        for (int j = 0; j < 4; j++) {
            size_t w = base + j;
            if (w < 393216) {
                int k2 = (int)(w / 1536), n = (int)(w % 1536);
                float a, b;
                if (n < 512) {
                    a = w_q[(size_t)(2 * k2) * 512 + n];
                    b = w_q[(size_t)(2 * k2 + 1) * 512 + n];
                } else {
                    int nn = n - 512;
                    a = w_kv[(size_t)(2 * k2) * 1024 + nn];
                    b = w_kv[(size_t)(2 * k2 + 1) * 1024 + nn];
                }
                g_WQKVp[w] = packh2(a, b);
            } else {
                size_t w2 = w - 393216;
                int k2 = (int)(w2 / 512), n = (int)(w2 % 512);
                g_WOp[w2] = packh2(w_out[(size_t)(2 * k2) * 512 + n],
                                   w_out[(size_t)(2 * k2 + 1) * 512 + n]);
            }
        }
    } else {
#pragma unroll
        for (int j = 0; j < 4; j++) {
            int t = threadIdx.x * 4 + j;
            float ang = (float)(t >> 5) * inv_freq[t & 31];
            g_cos[t] = cosf(ang);
            g_sin[t] = sinf(ang);
        }
        if (threadIdx.x == 0) {
            uint32_t w0 = m[0], w1 = m[1];
            if (w0 <= 1u && w1 <= 1u) {
                g_mask[0] = (int)w0; g_mask[1] = (int)w1;
            } else {
                const unsigned char* p = (const unsigned char*)m;
                g_mask[0] = p[0] ? 1 : 0; g_mask[1] = p[1] ? 1 : 0;
            }
        }
    }
}

// Epilogue store for the fused QKV GEMM (c in [0,1536), even; v0,v1 = c,c+1).
__device__ __forceinline__ void epi_store(int r, int c, float v0, float v1) {
    int seg = c >> 9;
    int off = c & 511;
    size_t p = (size_t)r * 256 + (off >> 1);
    if (seg == 2) {
        g_Vh[p] = packh2(v0, v1);
    } else {
        int pos = r & 31;
        int fi = (c & 63) >> 1;
        float cs = g_cos[pos * 32 + fi];
        float sn = g_sin[pos * 32 + fi];
        if (seg == 0) { v0 *= 0.125f; v1 *= 0.125f; }
        uint32_t w = packh2(v0 * cs - v1 * sn, v1 * cs + v0 * sn);
        ((seg == 0) ? g_Qh : g_Kh)[p] = w;
    }
}

// ---------------- fp16 mma.sync GEMM (round-8 champion config) ---------------
// C[M,N] = A[M,512]*B[512,N]; block 128x128, BK=64 (4 k16 steps, 8 chunks),
// 8 warps (2x4), warp tile 64x32 of m16n8k16, 2-stage cp.async, A via LDSM.
// A smem: uint32 pairs A[m][k2], 32 words/row + pad 4 -> stride 36 (LDSM CF)
// B smem: uint32 pairs B[k2][n], row stride 136 words (frag banks 8t+g: CF)
#define AS_STRIDE 36
#define BS_STRIDE 136
#define AS_WORDS (128 * AS_STRIDE)   // 4608
#define BS_WORDS (32 * BS_STRIDE)    // 4352
#define STG_WORDS (AS_WORDS + BS_WORDS)
#define GEMM_SMEM_BYTES (2 * STG_WORDS * 4)

template <int FUSED>
__global__ __launch_bounds__(256, 2) void gemm_kernel(float* __restrict__ Cout)
{
    extern __shared__ uint32_t sw[];

    const int rowBase = blockIdx.y * 128;
    // gemm2: masked batches have AO == V identically; attn skips them, so
    // read A from g_Vh there. Row blocks (128 rows) never straddle batches.
    const uint32_t* const Apack =
        FUSED ? g_Xp : (g_mask[rowBase >> 15] ? g_Vh : g_AOp);
    const uint32_t* const Bpack = FUSED ? g_WQKVp : g_WOp;

    const int tid = threadIdx.x;
    const int warp = tid >> 5, lane = tid & 31;
    const int wm = (warp >> 2) * 64, wn = (warp & 3) * 32;
    const int grp = lane >> 2, tig = lane & 3;
    const int bx = blockIdx.x;
    const int ldBp = FUSED ? 1536 : 512;
    const int nb = bx * 128;
    const uint32_t sbase = smem_u32(sw);

    auto ISSUE = [&](int c, int s) {
        const uint32_t stg = sbase + (uint32_t)s * STG_WORDS * 4;
#pragma unroll
        for (int i = 0; i < 4; i++) {
            int op = tid + 256 * i;
            int row = op >> 3, c4 = (op & 7) * 4;
            cp16(stg + (uint32_t)(row * AS_STRIDE + c4) * 4,
                 Apack + (size_t)(rowBase + row) * 256 + c * 32 + c4);
        }
#pragma unroll
        for (int i = 0; i < 4; i++) {
            int op = tid + 256 * i;
            int r = op >> 5, n4 = (op & 31) * 4;
            cp16(stg + (uint32_t)(AS_WORDS + r * BS_STRIDE + n4) * 4,
                 Bpack + (size_t)(c * 32 + r) * ldBp + nb + n4);
        }
    };

    const int lrow = lane & 15, lcolA = (lane >> 4) << 2;

    uint32_t af[4][4], bf[4][2];
    auto LOADFRAG = [&](int s, int ks) {
        const int k0 = ks * 8;
        const uint32_t aBase = sbase + (uint32_t)(s * STG_WORDS) * 4;
#pragma unroll
        for (int mf = 0; mf < 4; mf++) {
            uint32_t addr = aBase + (uint32_t)((wm + mf * 16 + lrow) * AS_STRIDE + k0 + lcolA) * 4;
            asm volatile(
                "ldmatrix.sync.aligned.m8n8.x4.shared.b16 {%0,%1,%2,%3}, [%4];"
                : "=r"(af[mf][0]), "=r"(af[mf][1]), "=r"(af[mf][2]), "=r"(af[mf][3])
                : "r"(addr));
        }
        const uint32_t* bs = sw + s * STG_WORDS + AS_WORDS;
#pragma unroll
        for (int nf = 0; nf < 4; nf++) {
            int nc = wn + nf * 8 + grp;
            bf[nf][0] = bs[(k0 + tig) * BS_STRIDE + nc];
            bf[nf][1] = bs[(k0 + tig + 4) * BS_STRIDE + nc];
        }
    };

    float acc[4][4][4];
#pragma unroll
    for (int a = 0; a < 4; a++)
#pragma unroll
        for (int b = 0; b < 4; b++)
#pragma unroll
            for (int c = 0; c < 4; c++) acc[a][b][c] = 0.0f;

    ISSUE(0, 0); cp_commit();

#pragma unroll 1
    for (int c = 0; c < 8; c++) {
        const int s = c & 1;
        asm volatile("cp.async.wait_group 0;" ::: "memory");
        __syncthreads();
        if (c < 7) { ISSUE(c + 1, s ^ 1); cp_commit(); }
#pragma unroll
        for (int ks = 0; ks < 4; ks++) {
            LOADFRAG(s, ks);
#pragma unroll
            for (int mf = 0; mf < 4; mf++)
#pragma unroll
                for (int nf = 0; nf < 4; nf++) {
                    asm volatile(
                        "mma.sync.aligned.m16n8k16.row.col.f32.f16.f16.f32 "
                        "{%0,%1,%2,%3}, {%4,%5,%6,%7}, {%8,%9}, {%0,%1,%2,%3};\n"
                        : "+f"(acc[mf][nf][0]), "+f"(acc[mf][nf][1]),
                          "+f"(acc[mf][nf][2]), "+f"(acc[mf][nf][3])
                        : "r"(af[mf][0]), "r"(af[mf][1]),
                          "r"(af[mf][2]), "r"(af[mf][3]),
                          "r"(bf[nf][0]), "r"(bf[nf][1]));
                }
        }
    }

    // -------- epilogue --------
    const int cBase = bx * 128 + wn;
#pragma unroll
    for (int mf = 0; mf < 4; mf++) {
        int r = rowBase + wm + mf * 16 + grp;
#pragma unroll
        for (int nf = 0; nf < 4; nf++) {
            int c = cBase + nf * 8 + 2 * tig;
            if (FUSED) {
                epi_store(r,     c, acc[mf][nf][0], acc[mf][nf][1]);
                epi_store(r + 8, c, acc[mf][nf][2], acc[mf][nf][3]);
            } else {
                *(float2*)(Cout + (size_t)r * 512 + c) =
                    make_float2(acc[mf][nf][0], acc[mf][nf][1]);
                *(float2*)(Cout + (size_t)(r + 8) * 512 + c) =
                    make_float2(acc[mf][nf][2], acc[mf][nf][3]);
            }
        }
    }
}

// ---------------- attention: 2 units per block, warp-local softmax/PV -------
// Unit = one (b,s,h): 32x32 attention over d=64. 128 threads per unit.
// Thread (i = ut>>2, jg = ut&3) computes sim for j in [8jg, 8jg+8); the 4
// threads of a row are adjacent lanes -> softmax reduce via 2 shfl_xor.
// sS rows of a warp are written and read within that warp -> __syncwarp only.
// Masked batches: early return (gemm2 reads g_Vh for those rows).
#define AU_WORDS (2176 + 2176 + 2304 + 1056)     // sQ[32][68] sK[32][68] sV[32][72] sS[32][33]
#define ATTN_SMEM_BYTES (2 * AU_WORDS * 4)       // 61696

__global__ __launch_bounds__(256) void attn_kernel(const float* __restrict__ pos_bias)
{
    const int blk = blockIdx.x;          // 8192 blocks = 16384 units / 2
    if (g_mask[blk >> 12]) return;       // both units share bs -> same batch

    extern __shared__ float as_[];
    const int tid = threadIdx.x;
    const int u = tid >> 7, ut = tid & 127;
    const int id = blk * 2 + u;          // (b,s,h) unit
    const int h = id & 7;
    const int r0 = (id >> 3) * 32;
    const int hw = h * 32;               // head offset in half2 words

    float* sQ = as_ + u * AU_WORDS;      // [32][68]
    float* sK = sQ + 2176;               // [32][68]
    float* sV = sK + 2176;               // [32][72]
    float* sS = sV + 2304;               // [32][33]

    // ---- load Q/K/V (fp16 -> fp32 smem) ----
#pragma unroll
    for (int it = 0; it < 2; it++) {
        int idx = ut + 128 * it;
        int row = idx >> 3, w4 = (idx & 7) * 4;   // 4 half2 words = 8 floats
        size_t p = (size_t)(r0 + row) * 256 + hw + w4;
        uint4 qw = *(const uint4*)&g_Qh[p];
        uint4 kw = *(const uint4*)&g_Kh[p];
        uint4 vw = *(const uint4*)&g_Vh[p];
        int d = w4 * 2;
        uint32_t qa[4] = {qw.x, qw.y, qw.z, qw.w};
        uint32_t ka[4] = {kw.x, kw.y, kw.z, kw.w};
        uint32_t va[4] = {vw.x, vw.y, vw.z, vw.w};
#pragma unroll
        for (int j = 0; j < 4; j++) {
            float2 q = unpackh2(qa[j]);
            float2 k = unpackh2(ka[j]);
            float2 v = unpackh2(va[j]);
            sQ[row * 68 + d + 2 * j] = q.x; sQ[row * 68 + d + 2 * j + 1] = q.y;
            sK[row * 68 + d + 2 * j] = k.x; sK[row * 68 + d + 2 * j + 1] = k.y;
            sV[row * 72 + d + 2 * j] = v.x; sV[row * 72 + d + 2 * j + 1] = v.y;
        }
    }
    __syncthreads();

    const int i = ut >> 2, jg = ut & 3, jb = jg * 8;

    // ---- sim: 8 dots per thread ----
    float s[8];
#pragma unroll
    for (int jj = 0; jj < 8; jj++) s[jj] = 0.f;
#pragma unroll
    for (int d4 = 0; d4 < 64; d4 += 4) {
        float4 q = *(const float4*)&sQ[i * 68 + d4];
#pragma unroll
        for (int jj = 0; jj < 8; jj++) {
            float4 k = *(const float4*)&sK[(jb + jj) * 68 + d4];
            s[jj] += q.x * k.x + q.y * k.y + q.z * k.z + q.w * k.w;
        }
    }
    {
        const float* pb = pos_bias + (size_t)h * 1024 + i * 32 + jb;
        float4 p0 = *(const float4*)pb;
        float4 p1 = *(const float4*)(pb + 4);
        s[0] += p0.x; s[1] += p0.y; s[2] += p0.z; s[3] += p0.w;
        s[4] += p1.x; s[5] += p1.y; s[6] += p1.z; s[7] += p1.w;
    }

    // ---- softmax (4-lane groups) ----
    float m = s[0];
#pragma unroll
    for (int jj = 1; jj < 8; jj++) m = fmaxf(m, s[jj]);
    m = fmaxf(m, __shfl_xor_sync(0xffffffffu, m, 1));
    m = fmaxf(m, __shfl_xor_sync(0xffffffffu, m, 2));
    float e[8], sum = 0.f;
#pragma unroll
    for (int jj = 0; jj < 8; jj++) { e[jj] = __expf(s[jj] - m); sum += e[jj]; }
    sum += __shfl_xor_sync(0xffffffffu, sum, 1);
    sum += __shfl_xor_sync(0xffffffffu, sum, 2);
    float inv = __frcp_rn(sum);
#pragma unroll
    for (int jj = 0; jj < 8; jj++) sS[i * 33 + jb + jj] = e[jj] * inv;
    __syncwarp();

    // ---- PV: thread (i, dg=jg) -> 16 d's ----
    const int d0 = jg * 16;
    float o[16];
#pragma unroll
    for (int dd = 0; dd < 16; dd++) o[dd] = 0.f;
#pragma unroll
    for (int j = 0; j < 32; j++) {
        float a = sS[i * 33 + j];
        const float* vr = &sV[j * 72 + d0];
        float4 v0 = *(const float4*)(vr + 0);
        float4 v1 = *(const float4*)(vr + 4);
        float4 v2 = *(const float4*)(vr + 8);
        float4 v3 = *(const float4*)(vr + 12);
        o[0]  += a * v0.x; o[1]  += a * v0.y; o[2]  += a * v0.z; o[3]  += a * v0.w;
        o[4]  += a * v1.x; o[5]  += a * v1.y; o[6]  += a * v1.z; o[7]  += a * v1.w;
        o[8]  += a * v2.x; o[9]  += a * v2.y; o[10] += a * v2.z; o[11] += a * v2.w;
        o[12] += a * v3.x; o[13] += a * v3.y; o[14] += a * v3.z; o[15] += a * v3.w;
    }
    size_t p = (size_t)(r0 + i) * 256 + hw + (d0 >> 1);
    uint4 w0 = make_uint4(packh2(o[0], o[1]),  packh2(o[2], o[3]),
                          packh2(o[4], o[5]),  packh2(o[6], o[7]));
    uint4 w1 = make_uint4(packh2(o[8], o[9]),  packh2(o[10], o[11]),
                          packh2(o[12], o[13]), packh2(o[14], o[15]));
    *(uint4*)&g_AOp[p]     = w0;
    *(uint4*)&g_AOp[p + 4] = w1;
}

// ---------------- launch ------------------------------------------------------
// Inputs resolved by element count (robust to metadata ordering); w_q vs w_out
// (both 262144) disambiguated by position relative to w_kv.
extern "C" void kernel_launch(void* const* d_in, const int* in_sizes, int n_in,
                              void* d_out, int out_size)
{
    (void)out_size;
    int ix = -1, ipb = -1, ifoc = -1, ikv = -1, iif = -1;
    int i262[2] = {-1, -1}; int n262 = 0;
    for (int i = 0; i < n_in; i++) {
        switch (in_sizes[i]) {
            case 33554432: ix = i; break;
            case 8192:     ipb = i; break;
            case 2:        ifoc = i; break;
            case 524288:   ikv = i; break;
            case 32:       iif = i; break;
            case 262144:   if (n262 < 2) i262[n262++] = i; break;
            default: break;
        }
    }
    int iq, io;
    if (n262 == 2 && i262[0] < ikv) { iq = i262[0]; io = i262[1]; }
    else                            { io = i262[0]; iq = i262[1]; }

    const float* x        = (const float*)d_in[ix];
    const float* pos_bias = (const float*)d_in[ipb];
    const uint32_t* mask  = (const uint32_t*)d_in[ifoc];
    const float* w_q      = (const float*)d_in[iq];
    const float* w_kv     = (const float*)d_in[ikv];
    const float* w_out    = (const float*)d_in[io];
    const float* inv_freq = (const float*)d_in[iif];
    float* out = (float*)d_out;

    cudaFuncSetAttribute(gemm_kernel<1>, cudaFuncAttributeMaxDynamicSharedMemorySize, GEMM_SMEM_BYTES);
    cudaFuncSetAttribute(gemm_kernel<0>, cudaFuncAttributeMaxDynamicSharedMemorySize, GEMM_SMEM_BYTES);
    cudaFuncSetAttribute(attn_kernel, cudaFuncAttributeMaxDynamicSharedMemorySize, ATTN_SMEM_BYTES);

    setup_kernel<<<16384 + 512 + 1, 256>>>(x, w_q, w_kv, w_out, inv_freq, mask);
    gemm_kernel<1><<<dim3(12, 512), 256, GEMM_SMEM_BYTES>>>(nullptr);
    attn_kernel<<<8192, 256, ATTN_SMEM_BYTES>>>(pos_bias);
    gemm_kernel<0><<<dim3(4, 512), 256, GEMM_SMEM_BYTES>>>(out);
}

// round 12
// speedup vs baseline: 1.1965x; 1.1965x over previous
#include <cuda_runtime.h>
#include <cuda_fp16.h>
#include <cstdint>

// Problem dims (fixed):
//  x: (2,1024,32,512) -> M = 65536 rows of K=512
//  QKV cols = 1536 (Q 0-511, K 512-1023, V 1024-1535), out proj N=512
#define M_TOTAL 65536

// ---------------- scratch (device globals; no runtime allocation) ----------
__device__ uint32_t g_Qh[(size_t)M_TOTAL * 256];    // roped+scaled Q, half2 along d
__device__ uint32_t g_Kh[(size_t)M_TOTAL * 256];    // roped K, half2 along d
__device__ uint32_t g_Vh[(size_t)M_TOTAL * 256];    // V, half2 along d
__device__ uint32_t g_Xp[(size_t)M_TOTAL * 256];    // x as half2 pairs along k
__device__ uint32_t g_AOp[(size_t)M_TOTAL * 256];   // attn out as half2 pairs
__device__ uint32_t g_WQKVp[256 * 1536];            // [k2][n] half2(w[2k2][n], w[2k2+1][n])
__device__ uint32_t g_WOp[256 * 512];
__device__ float    g_cos[1024];
__device__ float    g_sin[1024];
__device__ int      g_mask[2];

// ---------------- helpers ----------------------------------------------------
__device__ __forceinline__ uint32_t packh2(float lo, float hi) {
    __half2 h = __floats2half2_rn(lo, hi);
    return *reinterpret_cast<uint32_t*>(&h);
}
__device__ __forceinline__ float2 unpackh2(uint32_t w) {
    return __half22float2(*reinterpret_cast<__half2*>(&w));
}
__device__ __forceinline__ uint32_t smem_u32(const void* p) {
    uint32_t a;
    asm("{ .reg .u64 t; cvta.to.shared.u64 t, %1; cvt.u32.u64 %0, t; }"
        : "=r"(a) : "l"(p));
    return a;
}
__device__ __forceinline__ void cp16(uint32_t dst, const void* src) {
    asm volatile("cp.async.cg.shared.global [%0], [%1], 16;"
                 :: "r"(dst), "l"(src) : "memory");
}
__device__ __forceinline__ void cp_commit() {
    asm volatile("cp.async.commit_group;" ::: "memory");
}

// ---------------- setup: pack x/weights to fp16, rope table, mask -----------
__global__ void setup_kernel(
    const float* __restrict__ x,
    const float* __restrict__ w_q,
    const float* __restrict__ w_kv,
    const float* __restrict__ w_out,
    const float* __restrict__ inv_freq,
    const uint32_t* __restrict__ m)
{
    const int bid = blockIdx.x;
    if (bid < 16384) {
        size_t base = ((size_t)bid * 256 + threadIdx.x) * 4;
#pragma unroll
        for (int j = 0; j < 4; j++) {
            size_t w = base + j;
            float2 v = *(const float2*)(x + 2 * w);
            g_Xp[w] = packh2(v.x, v.y);
        }
    } else if (bid < 16384 + 512) {
        // weights, k-pair packed: qkv 256x1536 words, out 256x512 words
        size_t base = ((size_t)(bid - 16384) * 256 + threadIdx.x) * 4;
#pragma unroll
        for (int j = 0; j < 4; j++) {
            size_t w = base + j;
            if (w < 393216) {
                int k2 = (int)(w / 1536), n = (int)(w % 1536);
                float a, b;
                if (n < 512) {
                    a = w_q[(size_t)(2 * k2) * 512 + n];
                    b = w_q[(size_t)(2 * k2 + 1) * 512 + n];
                } else {
                    int nn = n - 512;
                    a = w_kv[(size_t)(2 * k2) * 1024 + nn];
                    b = w_kv[(size_t)(2 * k2 + 1) * 1024 + nn];
                }
                g_WQKVp[w] = packh2(a, b);
            } else {
                size_t w2 = w - 393216;
                int k2 = (int)(w2 / 512), n = (int)(w2 % 512);
                g_WOp[w2] = packh2(w_out[(size_t)(2 * k2) * 512 + n],
                                   w_out[(size_t)(2 * k2 + 1) * 512 + n]);
            }
        }
    } else {
#pragma unroll
        for (int j = 0; j < 4; j++) {
            int t = threadIdx.x * 4 + j;
            float ang = (float)(t >> 5) * inv_freq[t & 31];
            g_cos[t] = cosf(ang);
            g_sin[t] = sinf(ang);
        }
        if (threadIdx.x == 0) {
            uint32_t w0 = m[0], w1 = m[1];
            if (w0 <= 1u && w1 <= 1u) {
                g_mask[0] = (int)w0; g_mask[1] = (int)w1;
            } else {
                const unsigned char* p = (const unsigned char*)m;
                g_mask[0] = p[0] ? 1 : 0; g_mask[1] = p[1] ? 1 : 0;
            }
        }
    }
}

// Epilogue store for the fused QKV GEMM (c in [0,1536), even; v0,v1 = c,c+1).
__device__ __forceinline__ void epi_store(int r, int c, float v0, float v1) {
    int seg = c >> 9;
    int off = c & 511;
    size_t p = (size_t)r * 256 + (off >> 1);
    if (seg == 2) {
        g_Vh[p] = packh2(v0, v1);
    } else {
        int pos = r & 31;
        int fi = (c & 63) >> 1;
        float cs = g_cos[pos * 32 + fi];
        float sn = g_sin[pos * 32 + fi];
        if (seg == 0) { v0 *= 0.125f; v1 *= 0.125f; }
        uint32_t w = packh2(v0 * cs - v1 * sn, v1 * cs + v0 * sn);
        ((seg == 0) ? g_Qh : g_Kh)[p] = w;
    }
}

// ---------------- fp16 mma.sync GEMM (round-8 champion config) ---------------
// C[M,N] = A[M,512]*B[512,N]; block 128x128, BK=64 (4 k16 steps, 8 chunks),
// 8 warps (2x4), warp tile 64x32 of m16n8k16, 2-stage cp.async, A via LDSM.
// A smem: uint32 pairs A[m][k2], 32 words/row + pad 4 -> stride 36 (LDSM CF)
// B smem: uint32 pairs B[k2][n], row stride 136 words (frag banks 8t+g: CF)
#define AS_STRIDE 36
#define BS_STRIDE 136
#define AS_WORDS (128 * AS_STRIDE)   // 4608
#define BS_WORDS (32 * BS_STRIDE)    // 4352
#define STG_WORDS (AS_WORDS + BS_WORDS)
#define GEMM_SMEM_BYTES (2 * STG_WORDS * 4)

template <int FUSED>
__global__ __launch_bounds__(256, 2) void gemm_kernel(float* __restrict__ Cout)
{
    extern __shared__ uint32_t sw[];

    const int rowBase = blockIdx.y * 128;
    // gemm2: masked batches have AO == V identically; attn skips them, so
    // read A from g_Vh there. Row blocks (128 rows) never straddle batches.
    const uint32_t* const Apack =
        FUSED ? g_Xp : (g_mask[rowBase >> 15] ? g_Vh : g_AOp);
    const uint32_t* const Bpack = FUSED ? g_WQKVp : g_WOp;

    const int tid = threadIdx.x;
    const int warp = tid >> 5, lane = tid & 31;
    const int wm = (warp >> 2) * 64, wn = (warp & 3) * 32;
    const int grp = lane >> 2, tig = lane & 3;
    const int bx = blockIdx.x;
    const int ldBp = FUSED ? 1536 : 512;
    const int nb = bx * 128;
    const uint32_t sbase = smem_u32(sw);

    auto ISSUE = [&](int c, int s) {
        const uint32_t stg = sbase + (uint32_t)s * STG_WORDS * 4;
#pragma unroll
        for (int i = 0; i < 4; i++) {
            int op = tid + 256 * i;
            int row = op >> 3, c4 = (op & 7) * 4;
            cp16(stg + (uint32_t)(row * AS_STRIDE + c4) * 4,
                 Apack + (size_t)(rowBase + row) * 256 + c * 32 + c4);
        }
#pragma unroll
        for (int i = 0; i < 4; i++) {
            int op = tid + 256 * i;
            int r = op >> 5, n4 = (op & 31) * 4;
            cp16(stg + (uint32_t)(AS_WORDS + r * BS_STRIDE + n4) * 4,
                 Bpack + (size_t)(c * 32 + r) * ldBp + nb + n4);
        }
    };

    const int lrow = lane & 15, lcolA = (lane >> 4) << 2;

    uint32_t af[4][4], bf[4][2];
    auto LOADFRAG = [&](int s, int ks) {
        const int k0 = ks * 8;
        const uint32_t aBase = sbase + (uint32_t)(s * STG_WORDS) * 4;
#pragma unroll
        for (int mf = 0; mf < 4; mf++) {
            uint32_t addr = aBase + (uint32_t)((wm + mf * 16 + lrow) * AS_STRIDE + k0 + lcolA) * 4;
            asm volatile(
                "ldmatrix.sync.aligned.m8n8.x4.shared.b16 {%0,%1,%2,%3}, [%4];"
                : "=r"(af[mf][0]), "=r"(af[mf][1]), "=r"(af[mf][2]), "=r"(af[mf][3])
                : "r"(addr));
        }
        const uint32_t* bs = sw + s * STG_WORDS + AS_WORDS;
#pragma unroll
        for (int nf = 0; nf < 4; nf++) {
            int nc = wn + nf * 8 + grp;
            bf[nf][0] = bs[(k0 + tig) * BS_STRIDE + nc];
            bf[nf][1] = bs[(k0 + tig + 4) * BS_STRIDE + nc];
        }
    };

    float acc[4][4][4];
#pragma unroll
    for (int a = 0; a < 4; a++)
#pragma unroll
        for (int b = 0; b < 4; b++)
#pragma unroll
            for (int c = 0; c < 4; c++) acc[a][b][c] = 0.0f;

    ISSUE(0, 0); cp_commit();

#pragma unroll 1
    for (int c = 0; c < 8; c++) {
        const int s = c & 1;
        asm volatile("cp.async.wait_group 0;" ::: "memory");
        __syncthreads();
        if (c < 7) { ISSUE(c + 1, s ^ 1); cp_commit(); }
#pragma unroll
        for (int ks = 0; ks < 4; ks++) {
            LOADFRAG(s, ks);
#pragma unroll
            for (int mf = 0; mf < 4; mf++)
#pragma unroll
                for (int nf = 0; nf < 4; nf++) {
                    asm volatile(
                        "mma.sync.aligned.m16n8k16.row.col.f32.f16.f16.f32 "
                        "{%0,%1,%2,%3}, {%4,%5,%6,%7}, {%8,%9}, {%0,%1,%2,%3};\n"
                        : "+f"(acc[mf][nf][0]), "+f"(acc[mf][nf][1]),
                          "+f"(acc[mf][nf][2]), "+f"(acc[mf][nf][3])
                        : "r"(af[mf][0]), "r"(af[mf][1]),
                          "r"(af[mf][2]), "r"(af[mf][3]),
                          "r"(bf[nf][0]), "r"(bf[nf][1]));
                }
        }
    }

    // -------- epilogue --------
    const int cBase = bx * 128 + wn;
#pragma unroll
    for (int mf = 0; mf < 4; mf++) {
        int r = rowBase + wm + mf * 16 + grp;
#pragma unroll
        for (int nf = 0; nf < 4; nf++) {
            int c = cBase + nf * 8 + 2 * tig;
            if (FUSED) {
                epi_store(r,     c, acc[mf][nf][0], acc[mf][nf][1]);
                epi_store(r + 8, c, acc[mf][nf][2], acc[mf][nf][3]);
            } else {
                *(float2*)(Cout + (size_t)r * 512 + c) =
                    make_float2(acc[mf][nf][0], acc[mf][nf][1]);
                *(float2*)(Cout + (size_t)(r + 8) * 512 + c) =
                    make_float2(acc[mf][nf][2], acc[mf][nf][3]);
            }
        }
    }
}

// ---------------- attention: one block per (b,s,h) (round-8 body) -----------
// Reads fp16 Q/K/V, fp32 smem compute, writes packed half2 to g_AOp.
// Masked batches: early return (gemm2 reads g_Vh for those rows instead).
__global__ __launch_bounds__(256) void attn_kernel(const float* __restrict__ pos_bias)
{
    const int blk = blockIdx.x;        // 16384 = 2*1024*8
    const int h = blk & 7;
    const int bs = blk >> 3;
    const int b = bs >> 10;
    if (g_mask[b]) return;             // handled by gemm2 A-select (AO == V)

    const int r0 = bs * 32;
    const int tid = threadIdx.x;
    const int hw = h * 32;             // head offset in half2 words

    __shared__ float sQ[32][68];
    __shared__ float sK[32][68];
    __shared__ float sV[32][72];
    __shared__ float sS[32][33];

    {
        int row = tid >> 3, w4 = (tid & 7) * 4;   // 4 half2 words = 8 floats
        size_t p = (size_t)(r0 + row) * 256 + hw + w4;
        uint4 qw = *(const uint4*)&g_Qh[p];
        uint4 kw = *(const uint4*)&g_Kh[p];
        uint4 vw = *(const uint4*)&g_Vh[p];
        int d = w4 * 2;
        uint32_t qa[4] = {qw.x, qw.y, qw.z, qw.w};
        uint32_t ka[4] = {kw.x, kw.y, kw.z, kw.w};
        uint32_t va[4] = {vw.x, vw.y, vw.z, vw.w};
#pragma unroll
        for (int j = 0; j < 4; j++) {
            float2 q = unpackh2(qa[j]);
            float2 k = unpackh2(ka[j]);
            float2 v = unpackh2(va[j]);
            sQ[row][d + 2 * j]     = q.x; sQ[row][d + 2 * j + 1] = q.y;
            sK[row][d + 2 * j]     = k.x; sK[row][d + 2 * j + 1] = k.y;
            sV[row][d + 2 * j]     = v.x; sV[row][d + 2 * j + 1] = v.y;
        }
    }
    __syncthreads();

    // sim[i][j] = q_i . k_j + pos_bias; thread -> (i = tid>>3, j = (tid&7)+8r)
    const int i = tid >> 3;
    const int jb = tid & 7;
    float s0 = 0.f, s1 = 0.f, s2 = 0.f, s3 = 0.f;
#pragma unroll
    for (int d4 = 0; d4 < 64; d4 += 4) {
        float4 q = *(const float4*)&sQ[i][d4];
        float4 k0 = *(const float4*)&sK[jb][d4];
        float4 k1 = *(const float4*)&sK[jb + 8][d4];
        float4 k2 = *(const float4*)&sK[jb + 16][d4];
        float4 k3 = *(const float4*)&sK[jb + 24][d4];
        s0 += q.x * k0.x + q.y * k0.y + q.z * k0.z + q.w * k0.w;
        s1 += q.x * k1.x + q.y * k1.y + q.z * k1.z + q.w * k1.w;
        s2 += q.x * k2.x + q.y * k2.y + q.z * k2.z + q.w * k2.w;
        s3 += q.x * k3.x + q.y * k3.y + q.z * k3.z + q.w * k3.w;
    }
    const float* pb = pos_bias + (size_t)h * 1024 + i * 32 + jb;
    sS[i][jb +  0] = s0 + pb[0];
    sS[i][jb +  8] = s1 + pb[8];
    sS[i][jb + 16] = s2 + pb[16];
    sS[i][jb + 24] = s3 + pb[24];
    __syncthreads();

    // softmax: warp w -> rows 4w..4w+3, one lane per column
    const int warp = tid >> 5, lane = tid & 31;
#pragma unroll
    for (int rr = 0; rr < 4; rr++) {
        int row = warp * 4 + rr;
        float v = sS[row][lane];
        float m = v;
#pragma unroll
        for (int o = 16; o > 0; o >>= 1) m = fmaxf(m, __shfl_xor_sync(0xffffffffu, m, o));
        float e = __expf(v - m);
        float sum = e;
#pragma unroll
        for (int o = 16; o > 0; o >>= 1) sum += __shfl_xor_sync(0xffffffffu, sum, o);
        sS[row][lane] = e / sum;
    }
    __syncthreads();

    // out[i][d] = sum_j attn[i][j] * v[j][d]; thread -> (row i, 8 d's)
    const int db = (tid & 7) * 8;
    float4 o0 = make_float4(0.f, 0.f, 0.f, 0.f);
    float4 o1 = make_float4(0.f, 0.f, 0.f, 0.f);
#pragma unroll
    for (int j = 0; j < 32; j++) {
        float a = sS[i][j];
        float4 v0 = *(const float4*)&sV[j][db];
        float4 v1 = *(const float4*)&sV[j][db + 4];
        o0.x += a * v0.x; o0.y += a * v0.y; o0.z += a * v0.z; o0.w += a * v0.w;
        o1.x += a * v1.x; o1.y += a * v1.y; o1.z += a * v1.z; o1.w += a * v1.w;
    }
    uint4 w = make_uint4(packh2(o0.x, o0.y), packh2(o0.z, o0.w),
                         packh2(o1.x, o1.y), packh2(o1.z, o1.w));
    *(uint4*)&g_AOp[(size_t)(r0 + i) * 256 + hw + (db >> 1)] = w;
}

// ---------------- launch ------------------------------------------------------
// Inputs resolved by element count (robust to metadata ordering); w_q vs w_out
// (both 262144) disambiguated by position relative to w_kv.
extern "C" void kernel_launch(void* const* d_in, const int* in_sizes, int n_in,
                              void* d_out, int out_size)
{
    (void)out_size;
    int ix = -1, ipb = -1, ifoc = -1, ikv = -1, iif = -1;
    int i262[2] = {-1, -1}; int n262 = 0;
    for (int i = 0; i < n_in; i++) {
        switch (in_sizes[i]) {
            case 33554432: ix = i; break;
            case 8192:     ipb = i; break;
            case 2:        ifoc = i; break;
            case 524288:   ikv = i; break;
            case 32:       iif = i; break;
            case 262144:   if (n262 < 2) i262[n262++] = i; break;
            default: break;
        }
    }
    int iq, io;
    if (n262 == 2 && i262[0] < ikv) { iq = i262[0]; io = i262[1]; }
    else                            { io = i262[0]; iq = i262[1]; }

    const float* x        = (const float*)d_in[ix];
    const float* pos_bias = (const float*)d_in[ipb];
    const uint32_t* mask  = (const uint32_t*)d_in[ifoc];
    const float* w_q      = (const float*)d_in[iq];
    const float* w_kv     = (const float*)d_in[ikv];
    const float* w_out    = (const float*)d_in[io];
    const float* inv_freq = (const float*)d_in[iif];
    float* out = (float*)d_out;

    cudaFuncSetAttribute(gemm_kernel<1>, cudaFuncAttributeMaxDynamicSharedMemorySize, GEMM_SMEM_BYTES);
    cudaFuncSetAttribute(gemm_kernel<0>, cudaFuncAttributeMaxDynamicSharedMemorySize, GEMM_SMEM_BYTES);

    setup_kernel<<<16384 + 512 + 1, 256>>>(x, w_q, w_kv, w_out, inv_freq, mask);
    gemm_kernel<1><<<dim3(12, 512), 256, GEMM_SMEM_BYTES>>>(nullptr);
    attn_kernel<<<16384, 256>>>(pos_bias);
    gemm_kernel<0><<<dim3(4, 512), 256, GEMM_SMEM_BYTES>>>(out);
}

// round 14
// speedup vs baseline: 1.5816x; 1.3219x over previous
#include <cuda_runtime.h>
#include <cuda_fp16.h>
#include <cstdint>

// Problem dims (fixed):
//  x: (2,1024,32,512) -> M = 65536 rows of K=512
//  QKV cols = 1536 (Q 0-511, K 512-1023, V 1024-1535), out proj N=512
#define M_TOTAL 65536

// ---------------- scratch (device globals; no runtime allocation) ----------
__device__ uint32_t g_Qh[(size_t)M_TOTAL * 256];    // roped+scaled Q, half2 along d
__device__ uint32_t g_Kh[(size_t)M_TOTAL * 256];    // roped K, half2 along d
__device__ uint32_t g_Vh[(size_t)M_TOTAL * 256];    // V, half2 along d
__device__ uint32_t g_Xp[(size_t)M_TOTAL * 256];    // x as half2 pairs along k
__device__ uint32_t g_AOp[(size_t)M_TOTAL * 256];   // attn out as half2 pairs
__device__ uint32_t g_WQKVp[256 * 1536];            // [k2][n] half2(w[2k2][n], w[2k2+1][n])
__device__ uint32_t g_WOp[256 * 512];
__device__ float    g_cos[1024];
__device__ float    g_sin[1024];
__device__ int      g_mask[2];

// ---------------- helpers ----------------------------------------------------
__device__ __forceinline__ uint32_t packh2(float lo, float hi) {
    __half2 h = __floats2half2_rn(lo, hi);
    return *reinterpret_cast<uint32_t*>(&h);
}
__device__ __forceinline__ uint32_t smem_u32(const void* p) {
    uint32_t a;
    asm("{ .reg .u64 t; cvta.to.shared.u64 t, %1; cvt.u32.u64 %0, t; }"
        : "=r"(a) : "l"(p));
    return a;
}
__device__ __forceinline__ void cp16(uint32_t dst, const void* src) {
    asm volatile("cp.async.cg.shared.global [%0], [%1], 16;"
                 :: "r"(dst), "l"(src) : "memory");
}
__device__ __forceinline__ void cp_commit() {
    asm volatile("cp.async.commit_group;" ::: "memory");
}
#define MMA_F16(D, A, B0, B1)                                              \
    asm volatile(                                                          \
        "mma.sync.aligned.m16n8k16.row.col.f32.f16.f16.f32 "               \
        "{%0,%1,%2,%3}, {%4,%5,%6,%7}, {%8,%9}, {%0,%1,%2,%3};\n"          \
        : "+f"((D)[0]), "+f"((D)[1]), "+f"((D)[2]), "+f"((D)[3])           \
        : "r"((A)[0]), "r"((A)[1]), "r"((A)[2]), "r"((A)[3]),              \
          "r"(B0), "r"(B1))

// ---------------- setup: pack x/weights to fp16, rope table, mask -----------
__global__ void setup_kernel(
    const float* __restrict__ x,
    const float* __restrict__ w_q,
    const float* __restrict__ w_kv,
    const float* __restrict__ w_out,
    const float* __restrict__ inv_freq,
    const uint32_t* __restrict__ m)
{
    const int bid = blockIdx.x;
    if (bid < 16384) {
        size_t base = ((size_t)bid * 256 + threadIdx.x) * 4;
#pragma unroll
        for (int j = 0; j < 4; j++) {
            size_t w = base + j;
            float2 v = *(const float2*)(x + 2 * w);
            g_Xp[w] = packh2(v.x, v.y);
        }
    } else if (bid < 16384 + 512) {
        // weights, k-pair packed: qkv 256x1536 words, out 256x512 words
        size_t base = ((size_t)(bid - 16384) * 256 + threadIdx.x) * 4;
#pragma unroll
        for (int j = 0; j < 4; j++) {
            size_t w = base + j;
            if (w < 393216) {
                int k2 = (int)(w / 1536), n = (int)(w % 1536);
                float a, b;
                if (n < 512) {
                    a = w_q[(size_t)(2 * k2) * 512 + n];
                    b = w_q[(size_t)(2 * k2 + 1) * 512 + n];
                } else {
                    int nn = n - 512;
                    a = w_kv[(size_t)(2 * k2) * 1024 + nn];
                    b = w_kv[(size_t)(2 * k2 + 1) * 1024 + nn];
                }
                g_WQKVp[w] = packh2(a, b);
            } else {
                size_t w2 = w - 393216;
                int k2 = (int)(w2 / 512), n = (int)(w2 % 512);
                g_WOp[w2] = packh2(w_out[(size_t)(2 * k2) * 512 + n],
                                   w_out[(size_t)(2 * k2 + 1) * 512 + n]);
            }
        }
    } else {
#pragma unroll
        for (int j = 0; j < 4; j++) {
            int t = threadIdx.x * 4 + j;
            float ang = (float)(t >> 5) * inv_freq[t & 31];
            g_cos[t] = cosf(ang);
            g_sin[t] = sinf(ang);
        }
        if (threadIdx.x == 0) {
            uint32_t w0 = m[0], w1 = m[1];
            if (w0 <= 1u && w1 <= 1u) {
                g_mask[0] = (int)w0; g_mask[1] = (int)w1;
            } else {
                const unsigned char* p = (const unsigned char*)m;
                g_mask[0] = p[0] ? 1 : 0; g_mask[1] = p[1] ? 1 : 0;
            }
        }
    }
}

// Epilogue store for the fused QKV GEMM (c in [0,1536), even; v0,v1 = c,c+1).
__device__ __forceinline__ void epi_store(int r, int c, float v0, float v1) {
    int seg = c >> 9;
    int off = c & 511;
    size_t p = (size_t)r * 256 + (off >> 1);
    if (seg == 2) {
        g_Vh[p] = packh2(v0, v1);
    } else {
        int pos = r & 31;
        int fi = (c & 63) >> 1;
        float cs = g_cos[pos * 32 + fi];
        float sn = g_sin[pos * 32 + fi];
        if (seg == 0) { v0 *= 0.125f; v1 *= 0.125f; }
        uint32_t w = packh2(v0 * cs - v1 * sn, v1 * cs + v0 * sn);
        ((seg == 0) ? g_Qh : g_Kh)[p] = w;
    }
}

// ---------------- fp16 mma.sync GEMM (round-8 champion config) ---------------
// C[M,N] = A[M,512]*B[512,N]; block 128x128, BK=64 (4 k16 steps, 8 chunks),
// 8 warps (2x4), warp tile 64x32 of m16n8k16, 2-stage cp.async, A via LDSM.
#define AS_STRIDE 36
#define BS_STRIDE 136
#define AS_WORDS (128 * AS_STRIDE)   // 4608
#define BS_WORDS (32 * BS_STRIDE)    // 4352
#define STG_WORDS (AS_WORDS + BS_WORDS)
#define GEMM_SMEM_BYTES (2 * STG_WORDS * 4)

template <int FUSED>
__global__ __launch_bounds__(256, 2) void gemm_kernel(float* __restrict__ Cout)
{
    extern __shared__ uint32_t sw[];

    const int rowBase = blockIdx.y * 128;
    // gemm2: masked batches have AO == V identically; attn skips them, so
    // read A from g_Vh there. Row blocks (128 rows) never straddle batches.
    const uint32_t* const Apack =
        FUSED ? g_Xp : (g_mask[rowBase >> 15] ? g_Vh : g_AOp);
    const uint32_t* const Bpack = FUSED ? g_WQKVp : g_WOp;

    const int tid = threadIdx.x;
    const int warp = tid >> 5, lane = tid & 31;
    const int wm = (warp >> 2) * 64, wn = (warp & 3) * 32;
    const int grp = lane >> 2, tig = lane & 3;
    const int bx = blockIdx.x;
    const int ldBp = FUSED ? 1536 : 512;
    const int nb = bx * 128;
    const uint32_t sbase = smem_u32(sw);

    auto ISSUE = [&](int c, int s) {
        const uint32_t stg = sbase + (uint32_t)s * STG_WORDS * 4;
#pragma unroll
        for (int i = 0; i < 4; i++) {
            int op = tid + 256 * i;
            int row = op >> 3, c4 = (op & 7) * 4;
            cp16(stg + (uint32_t)(row * AS_STRIDE + c4) * 4,
                 Apack + (size_t)(rowBase + row) * 256 + c * 32 + c4);
        }
#pragma unroll
        for (int i = 0; i < 4; i++) {
            int op = tid + 256 * i;
            int r = op >> 5, n4 = (op & 31) * 4;
            cp16(stg + (uint32_t)(AS_WORDS + r * BS_STRIDE + n4) * 4,
                 Bpack + (size_t)(c * 32 + r) * ldBp + nb + n4);
        }
    };

    const int lrow = lane & 15, lcolA = (lane >> 4) << 2;

    uint32_t af[4][4], bf[4][2];
    auto LOADFRAG = [&](int s, int ks) {
        const int k0 = ks * 8;
        const uint32_t aBase = sbase + (uint32_t)(s * STG_WORDS) * 4;
#pragma unroll
        for (int mf = 0; mf < 4; mf++) {
            uint32_t addr = aBase + (uint32_t)((wm + mf * 16 + lrow) * AS_STRIDE + k0 + lcolA) * 4;
            asm volatile(
                "ldmatrix.sync.aligned.m8n8.x4.shared.b16 {%0,%1,%2,%3}, [%4];"
                : "=r"(af[mf][0]), "=r"(af[mf][1]), "=r"(af[mf][2]), "=r"(af[mf][3])
                : "r"(addr));
        }
        const uint32_t* bs = sw + s * STG_WORDS + AS_WORDS;
#pragma unroll
        for (int nf = 0; nf < 4; nf++) {
            int nc = wn + nf * 8 + grp;
            bf[nf][0] = bs[(k0 + tig) * BS_STRIDE + nc];
            bf[nf][1] = bs[(k0 + tig + 4) * BS_STRIDE + nc];
        }
    };

    float acc[4][4][4];
#pragma unroll
    for (int a = 0; a < 4; a++)
#pragma unroll
        for (int b = 0; b < 4; b++)
#pragma unroll
            for (int c = 0; c < 4; c++) acc[a][b][c] = 0.0f;

    ISSUE(0, 0); cp_commit();

#pragma unroll 1
    for (int c = 0; c < 8; c++) {
        const int s = c & 1;
        asm volatile("cp.async.wait_group 0;" ::: "memory");
        __syncthreads();
        if (c < 7) { ISSUE(c + 1, s ^ 1); cp_commit(); }
#pragma unroll
        for (int ks = 0; ks < 4; ks++) {
            LOADFRAG(s, ks);
#pragma unroll
            for (int mf = 0; mf < 4; mf++)
#pragma unroll
                for (int nf = 0; nf < 4; nf++)
                    MMA_F16(acc[mf][nf], af[mf], bf[nf][0], bf[nf][1]);
        }
    }

    // -------- epilogue --------
    const int cBase = bx * 128 + wn;
#pragma unroll
    for (int mf = 0; mf < 4; mf++) {
        int r = rowBase + wm + mf * 16 + grp;
#pragma unroll
        for (int nf = 0; nf < 4; nf++) {
            int c = cBase + nf * 8 + 2 * tig;
            if (FUSED) {
                epi_store(r,     c, acc[mf][nf][0], acc[mf][nf][1]);
                epi_store(r + 8, c, acc[mf][nf][2], acc[mf][nf][3]);
            } else {
                *(float2*)(Cout + (size_t)r * 512 + c) =
                    make_float2(acc[mf][nf][0], acc[mf][nf][1]);
                *(float2*)(Cout + (size_t)(r + 8) * 512 + c) =
                    make_float2(acc[mf][nf][2], acc[mf][nf][3]);
            }
        }
    }
}

// ---------------- attention: tensor-core, one warp per (b,s,h) --------------
// sim = Q K^T via m16n8k16 (Q/K fragments LDG'd straight from global: the
// d-contiguous half2 layout IS the fragment layout). Softmax on C-frags
// (4-lane shfl groups). P repacked to A-frags in registers. PV via V smem +
// trans-LDSM (round-9-validated mapping). No __syncthreads; masked warps exit.
#define SV_STRIDE 36

__global__ __launch_bounds__(128) void attn_kernel(const float* __restrict__ pos_bias)
{
    __shared__ uint32_t sV[4][32 * SV_STRIDE];

    const int tid = threadIdx.x;
    const int wid = tid >> 5, lane = tid & 31;
    const int unit = blockIdx.x * 4 + wid;     // 16384 units
    const int h = unit & 7;
    const int bs = unit >> 3;
    if (g_mask[bs >> 10]) return;              // gemm2 reads g_Vh for these

    const int r0 = bs * 32;
    const int hw = h * 32;                     // head offset in half2 words
    const int g = lane >> 2, t = lane & 3;

    // ---- stage V into per-warp smem (coalesced) ----
    uint32_t* sv = sV[wid];
#pragma unroll
    for (int it = 0; it < 8; it++) {
        int idx = lane + 32 * it;              // 256 uint4 ops
        int row = idx >> 3, w4 = (idx & 7) * 4;
        *(uint4*)&sv[row * SV_STRIDE + w4] =
            *(const uint4*)&g_Vh[(size_t)(r0 + row) * 256 + hw + w4];
    }
    __syncwarp();

    // ---- sim = Q K^T : C[mf][nf][4], kt over d (4 x k16) ----
    float C[2][4][4];
#pragma unroll
    for (int a = 0; a < 2; a++)
#pragma unroll
        for (int b = 0; b < 4; b++)
#pragma unroll
            for (int c = 0; c < 4; c++) C[a][b][c] = 0.f;

#pragma unroll
    for (int kt = 0; kt < 4; kt++) {
        uint32_t aq[2][4], bk[4][2];
#pragma unroll
        for (int mf = 0; mf < 2; mf++) {
            const uint32_t* q0 = &g_Qh[(size_t)(r0 + 16 * mf + g) * 256 + hw + 8 * kt + t];
            const uint32_t* q8 = &g_Qh[(size_t)(r0 + 16 * mf + g + 8) * 256 + hw + 8 * kt + t];
            aq[mf][0] = q0[0]; aq[mf][1] = q8[0];
            aq[mf][2] = q0[4]; aq[mf][3] = q8[4];
        }
#pragma unroll
        for (int nf = 0; nf < 4; nf++) {
            const uint32_t* kr = &g_Kh[(size_t)(r0 + 8 * nf + g) * 256 + hw + 8 * kt + t];
            bk[nf][0] = kr[0]; bk[nf][1] = kr[4];
        }
#pragma unroll
        for (int mf = 0; mf < 2; mf++)
#pragma unroll
            for (int nf = 0; nf < 4; nf++)
                MMA_F16(C[mf][nf], aq[mf], bk[nf][0], bk[nf][1]);
    }

    // ---- + pos_bias, softmax per row (rows g,g+8 per mf; 4-lane groups) ----
#pragma unroll
    for (int mf = 0; mf < 2; mf++) {
        float mA = -1e30f, mB = -1e30f;
#pragma unroll
        for (int nf = 0; nf < 4; nf++) {
            const float* pb = pos_bias + (size_t)h * 1024 + (16 * mf + g) * 32 + 8 * nf + 2 * t;
            float2 p0 = *(const float2*)pb;
            float2 p1 = *(const float2*)(pb + 8 * 32);   // row +8
            C[mf][nf][0] += p0.x; C[mf][nf][1] += p0.y;
            C[mf][nf][2] += p1.x; C[mf][nf][3] += p1.y;
            mA = fmaxf(mA, fmaxf(C[mf][nf][0], C[mf][nf][1]));
            mB = fmaxf(mB, fmaxf(C[mf][nf][2], C[mf][nf][3]));
        }
        mA = fmaxf(mA, __shfl_xor_sync(0xffffffffu, mA, 1));
        mA = fmaxf(mA, __shfl_xor_sync(0xffffffffu, mA, 2));
        mB = fmaxf(mB, __shfl_xor_sync(0xffffffffu, mB, 1));
        mB = fmaxf(mB, __shfl_xor_sync(0xffffffffu, mB, 2));
        float sA = 0.f, sB = 0.f;
#pragma unroll
        for (int nf = 0; nf < 4; nf++) {
            C[mf][nf][0] = __expf(C[mf][nf][0] - mA);
            C[mf][nf][1] = __expf(C[mf][nf][1] - mA);
            C[mf][nf][2] = __expf(C[mf][nf][2] - mB);
            C[mf][nf][3] = __expf(C[mf][nf][3] - mB);
            sA += C[mf][nf][0] + C[mf][nf][1];
            sB += C[mf][nf][2] + C[mf][nf][3];
        }
        sA += __shfl_xor_sync(0xffffffffu, sA, 1);
        sA += __shfl_xor_sync(0xffffffffu, sA, 2);
        sB += __shfl_xor_sync(0xffffffffu, sB, 1);
        sB += __shfl_xor_sync(0xffffffffu, sB, 2);
        float iA = __frcp_rn(sA), iB = __frcp_rn(sB);
#pragma unroll
        for (int nf = 0; nf < 4; nf++) {
            C[mf][nf][0] *= iA; C[mf][nf][1] *= iA;
            C[mf][nf][2] *= iB; C[mf][nf][3] *= iB;
        }
    }

    // ---- pack P into A-frags: P[kt][mf], kt over j (2 x k16) ----
    uint32_t P[2][2][4];
#pragma unroll
    for (int kt = 0; kt < 2; kt++)
#pragma unroll
        for (int mf = 0; mf < 2; mf++) {
            P[kt][mf][0] = packh2(C[mf][2 * kt][0],     C[mf][2 * kt][1]);
            P[kt][mf][1] = packh2(C[mf][2 * kt][2],     C[mf][2 * kt][3]);
            P[kt][mf][2] = packh2(C[mf][2 * kt + 1][0], C[mf][2 * kt + 1][1]);
            P[kt][mf][3] = packh2(C[mf][2 * kt + 1][2], C[mf][2 * kt + 1][3]);
        }

    // ---- PV: B-frags from V smem via trans-LDSM; 2 n-tiles per nf2 ----
    const int lrow = lane & 15, bcol8 = (lane >> 4) << 3;
    const uint32_t svb = smem_u32(sv);
#pragma unroll
    for (int nf2 = 0; nf2 < 4; nf2++) {
        uint32_t b0[4], b1[4];
        uint32_t a0 = svb + (uint32_t)((lrow)      * SV_STRIDE + ((nf2 * 16 + bcol8) >> 1)) * 4;
        uint32_t a1 = svb + (uint32_t)((16 + lrow) * SV_STRIDE + ((nf2 * 16 + bcol8) >> 1)) * 4;
        asm volatile(
            "ldmatrix.sync.aligned.m8n8.x4.trans.shared.b16 {%0,%1,%2,%3}, [%4];"
            : "=r"(b0[0]), "=r"(b0[1]), "=r"(b0[2]), "=r"(b0[3]) : "r"(a0));
        asm volatile(
            "ldmatrix.sync.aligned.m8n8.x4.trans.shared.b16 {%0,%1,%2,%3}, [%4];"
            : "=r"(b1[0]), "=r"(b1[1]), "=r"(b1[2]), "=r"(b1[3]) : "r"(a1));

        float O[2][2][4];
#pragma unroll
        for (int a = 0; a < 2; a++)
#pragma unroll
            for (int b = 0; b < 2; b++)
#pragma unroll
                for (int c = 0; c < 4; c++) O[a][b][c] = 0.f;
#pragma unroll
        for (int mf = 0; mf < 2; mf++)
#pragma unroll
            for (int nt = 0; nt < 2; nt++) {
                MMA_F16(O[mf][nt], P[0][mf], b0[2 * nt], b0[2 * nt + 1]);
                MMA_F16(O[mf][nt], P[1][mf], b1[2 * nt], b1[2 * nt + 1]);
            }
        // store: n-tile (2nf2+nt) -> d word (2nf2+nt)*4 + t
#pragma unroll
        for (int mf = 0; mf < 2; mf++)
#pragma unroll
            for (int nt = 0; nt < 2; nt++) {
                int wordc = hw + (2 * nf2 + nt) * 4 + t;
                g_AOp[(size_t)(r0 + 16 * mf + g)     * 256 + wordc] = packh2(O[mf][nt][0], O[mf][nt][1]);
                g_AOp[(size_t)(r0 + 16 * mf + g + 8) * 256 + wordc] = packh2(O[mf][nt][2], O[mf][nt][3]);
            }
    }
}

// ---------------- launch ------------------------------------------------------
// Inputs resolved by element count (robust to metadata ordering); w_q vs w_out
// (both 262144) disambiguated by position relative to w_kv.
extern "C" void kernel_launch(void* const* d_in, const int* in_sizes, int n_in,
                              void* d_out, int out_size)
{
    (void)out_size;
    int ix = -1, ipb = -1, ifoc = -1, ikv = -1, iif = -1;
    int i262[2] = {-1, -1}; int n262 = 0;
    for (int i = 0; i < n_in; i++) {
        switch (in_sizes[i]) {
            case 33554432: ix = i; break;
            case 8192:     ipb = i; break;
            case 2:        ifoc = i; break;
            case 524288:   ikv = i; break;
            case 32:       iif = i; break;
            case 262144:   if (n262 < 2) i262[n262++] = i; break;
            default: break;
        }
    }
    int iq, io;
    if (n262 == 2 && i262[0] < ikv) { iq = i262[0]; io = i262[1]; }
    else                            { io = i262[0]; iq = i262[1]; }

    const float* x        = (const float*)d_in[ix];
    const float* pos_bias = (const float*)d_in[ipb];
    const uint32_t* mask  = (const uint32_t*)d_in[ifoc];
    const float* w_q      = (const float*)d_in[iq];
    const float* w_kv     = (const float*)d_in[ikv];
    const float* w_out    = (const float*)d_in[io];
    const float* inv_freq = (const float*)d_in[iif];
    float* out = (float*)d_out;

    cudaFuncSetAttribute(gemm_kernel<1>, cudaFuncAttributeMaxDynamicSharedMemorySize, GEMM_SMEM_BYTES);
    cudaFuncSetAttribute(gemm_kernel<0>, cudaFuncAttributeMaxDynamicSharedMemorySize, GEMM_SMEM_BYTES);

    setup_kernel<<<16384 + 512 + 1, 256>>>(x, w_q, w_kv, w_out, inv_freq, mask);
    gemm_kernel<1><<<dim3(12, 512), 256, GEMM_SMEM_BYTES>>>(nullptr);
    attn_kernel<<<4096, 128>>>(pos_bias);
    gemm_kernel<0><<<dim3(4, 512), 256, GEMM_SMEM_BYTES>>>(out);
}

// round 15
// speedup vs baseline: 1.5845x; 1.0018x over previous
#include <cuda_runtime.h>
#include <cuda_fp16.h>
#include <cstdint>

// Problem dims (fixed):
//  x: (2,1024,32,512) -> M = 65536 rows of K=512
//  QKV cols = 1536 (Q 0-511, K 512-1023, V 1024-1535), out proj N=512
#define M_TOTAL 65536

// ---------------- scratch (device globals; no runtime allocation) ----------
__device__ uint32_t g_Qh[(size_t)M_TOTAL * 256];    // roped+scaled Q, half2 along d
__device__ uint32_t g_Kh[(size_t)M_TOTAL * 256];    // roped K, half2 along d
__device__ uint32_t g_Vh[(size_t)M_TOTAL * 256];    // V, half2 along d
__device__ uint32_t g_Xp[(size_t)M_TOTAL * 256];    // x as half2 pairs along k
__device__ uint32_t g_AOp[(size_t)M_TOTAL * 256];   // attn out as half2 pairs
__device__ uint32_t g_WQKVp[256 * 1536];            // [k2][n] half2(w[2k2][n], w[2k2+1][n])
__device__ uint32_t g_WOp[256 * 512];
__device__ float    g_cos[1024];
__device__ float    g_sin[1024];
__device__ int      g_mask[2];

// ---------------- helpers ----------------------------------------------------
__device__ __forceinline__ uint32_t packh2(float lo, float hi) {
    __half2 h = __floats2half2_rn(lo, hi);
    return *reinterpret_cast<uint32_t*>(&h);
}
__device__ __forceinline__ uint32_t smem_u32(const void* p) {
    uint32_t a;
    asm("{ .reg .u64 t; cvta.to.shared.u64 t, %1; cvt.u32.u64 %0, t; }"
        : "=r"(a) : "l"(p));
    return a;
}
__device__ __forceinline__ void cp16(uint32_t dst, const void* src) {
    asm volatile("cp.async.cg.shared.global [%0], [%1], 16;"
                 :: "r"(dst), "l"(src) : "memory");
}
__device__ __forceinline__ void cp_commit() {
    asm volatile("cp.async.commit_group;" ::: "memory");
}
#define MMA_F16(D, A, B0, B1)                                              \
    asm volatile(                                                          \
        "mma.sync.aligned.m16n8k16.row.col.f32.f16.f16.f32 "               \
        "{%0,%1,%2,%3}, {%4,%5,%6,%7}, {%8,%9}, {%0,%1,%2,%3};\n"          \
        : "+f"((D)[0]), "+f"((D)[1]), "+f"((D)[2]), "+f"((D)[3])           \
        : "r"((A)[0]), "r"((A)[1]), "r"((A)[2]), "r"((A)[3]),              \
          "r"(B0), "r"(B1))

// ---------------- setup: pack x/weights to fp16, rope table, mask -----------
__global__ void setup_kernel(
    const float* __restrict__ x,
    const float* __restrict__ w_q,
    const float* __restrict__ w_kv,
    const float* __restrict__ w_out,
    const float* __restrict__ inv_freq,
    const uint32_t* __restrict__ m)
{
    const int bid = blockIdx.x;
    if (bid < 16384) {
        size_t base = ((size_t)bid * 256 + threadIdx.x) * 4;
#pragma unroll
        for (int j = 0; j < 4; j++) {
            size_t w = base + j;
            float2 v = *(const float2*)(x + 2 * w);
            g_Xp[w] = packh2(v.x, v.y);
        }
    } else if (bid < 16384 + 512) {
        // weights, k-pair packed: qkv 256x1536 words, out 256x512 words
        size_t base = ((size_t)(bid - 16384) * 256 + threadIdx.x) * 4;
#pragma unroll
        for (int j = 0; j < 4; j++) {
            size_t w = base + j;
            if (w < 393216) {
                int k2 = (int)(w / 1536), n = (int)(w % 1536);
                float a, b;
                if (n < 512) {
                    a = w_q[(size_t)(2 * k2) * 512 + n];
                    b = w_q[(size_t)(2 * k2 + 1) * 512 + n];
                } else {
                    int nn = n - 512;
                    a = w_kv[(size_t)(2 * k2) * 1024 + nn];
                    b = w_kv[(size_t)(2 * k2 + 1) * 1024 + nn];
                }
                g_WQKVp[w] = packh2(a, b);
            } else {
                size_t w2 = w - 393216;
                int k2 = (int)(w2 / 512), n = (int)(w2 % 512);
                g_WOp[w2] = packh2(w_out[(size_t)(2 * k2) * 512 + n],
                                   w_out[(size_t)(2 * k2 + 1) * 512 + n]);
            }
        }
    } else {
#pragma unroll
        for (int j = 0; j < 4; j++) {
            int t = threadIdx.x * 4 + j;
            float ang = (float)(t >> 5) * inv_freq[t & 31];
            g_cos[t] = cosf(ang);
            g_sin[t] = sinf(ang);
        }
        if (threadIdx.x == 0) {
            uint32_t w0 = m[0], w1 = m[1];
            if (w0 <= 1u && w1 <= 1u) {
                g_mask[0] = (int)w0; g_mask[1] = (int)w1;
            } else {
                const unsigned char* p = (const unsigned char*)m;
                g_mask[0] = p[0] ? 1 : 0; g_mask[1] = p[1] ? 1 : 0;
            }
        }
    }
}

// Epilogue store for the fused QKV GEMM (c in [0,1536), even; v0,v1 = c,c+1).
__device__ __forceinline__ void epi_store(int r, int c, float v0, float v1) {
    int seg = c >> 9;
    int off = c & 511;
    size_t p = (size_t)r * 256 + (off >> 1);
    if (seg == 2) {
        g_Vh[p] = packh2(v0, v1);
    } else {
        int pos = r & 31;
        int fi = (c & 63) >> 1;
        float cs = g_cos[pos * 32 + fi];
        float sn = g_sin[pos * 32 + fi];
        if (seg == 0) { v0 *= 0.125f; v1 *= 0.125f; }
        uint32_t w = packh2(v0 * cs - v1 * sn, v1 * cs + v0 * sn);
        ((seg == 0) ? g_Qh : g_Kh)[p] = w;
    }
}

// ---------------- fp16 mma.sync GEMM (round-8 champion config) ---------------
// C[M,N] = A[M,512]*B[512,N]; block 128x128, BK=64 (4 k16 steps, 8 chunks),
// 8 warps (2x4), warp tile 64x32 of m16n8k16, 2-stage cp.async, A via LDSM.
#define AS_STRIDE 36
#define BS_STRIDE 136
#define AS_WORDS (128 * AS_STRIDE)   // 4608
#define BS_WORDS (32 * BS_STRIDE)    // 4352
#define STG_WORDS (AS_WORDS + BS_WORDS)
#define GEMM_SMEM_BYTES (2 * STG_WORDS * 4)

template <int FUSED>
__global__ __launch_bounds__(256, 2) void gemm_kernel(float* __restrict__ Cout)
{
    extern __shared__ uint32_t sw[];

    const int rowBase = blockIdx.y * 128;
    // gemm2: masked batches have AO == V identically; attn skips them, so
    // read A from g_Vh there. Row blocks (128 rows) never straddle batches.
    const uint32_t* const Apack =
        FUSED ? g_Xp : (g_mask[rowBase >> 15] ? g_Vh : g_AOp);
    const uint32_t* const Bpack = FUSED ? g_WQKVp : g_WOp;

    const int tid = threadIdx.x;
    const int warp = tid >> 5, lane = tid & 31;
    const int wm = (warp >> 2) * 64, wn = (warp & 3) * 32;
    const int grp = lane >> 2, tig = lane & 3;
    const int bx = blockIdx.x;
    const int ldBp = FUSED ? 1536 : 512;
    const int nb = bx * 128;
    const uint32_t sbase = smem_u32(sw);

    auto ISSUE = [&](int c, int s) {
        const uint32_t stg = sbase + (uint32_t)s * STG_WORDS * 4;
#pragma unroll
        for (int i = 0; i < 4; i++) {
            int op = tid + 256 * i;
            int row = op >> 3, c4 = (op & 7) * 4;
            cp16(stg + (uint32_t)(row * AS_STRIDE + c4) * 4,
                 Apack + (size_t)(rowBase + row) * 256 + c * 32 + c4);
        }
#pragma unroll
        for (int i = 0; i < 4; i++) {
            int op = tid + 256 * i;
            int r = op >> 5, n4 = (op & 31) * 4;
            cp16(stg + (uint32_t)(AS_WORDS + r * BS_STRIDE + n4) * 4,
                 Bpack + (size_t)(c * 32 + r) * ldBp + nb + n4);
        }
    };

    const int lrow = lane & 15, lcolA = (lane >> 4) << 2;

    uint32_t af[4][4], bf[4][2];
    auto LOADFRAG = [&](int s, int ks) {
        const int k0 = ks * 8;
        const uint32_t aBase = sbase + (uint32_t)(s * STG_WORDS) * 4;
#pragma unroll
        for (int mf = 0; mf < 4; mf++) {
            uint32_t addr = aBase + (uint32_t)((wm + mf * 16 + lrow) * AS_STRIDE + k0 + lcolA) * 4;
            asm volatile(
                "ldmatrix.sync.aligned.m8n8.x4.shared.b16 {%0,%1,%2,%3}, [%4];"
                : "=r"(af[mf][0]), "=r"(af[mf][1]), "=r"(af[mf][2]), "=r"(af[mf][3])
                : "r"(addr));
        }
        const uint32_t* bs = sw + s * STG_WORDS + AS_WORDS;
#pragma unroll
        for (int nf = 0; nf < 4; nf++) {
            int nc = wn + nf * 8 + grp;
            bf[nf][0] = bs[(k0 + tig) * BS_STRIDE + nc];
            bf[nf][1] = bs[(k0 + tig + 4) * BS_STRIDE + nc];
        }
    };

    float acc[4][4][4];
#pragma unroll
    for (int a = 0; a < 4; a++)
#pragma unroll
        for (int b = 0; b < 4; b++)
#pragma unroll
            for (int c = 0; c < 4; c++) acc[a][b][c] = 0.0f;

    ISSUE(0, 0); cp_commit();

#pragma unroll 1
    for (int c = 0; c < 8; c++) {
        const int s = c & 1;
        asm volatile("cp.async.wait_group 0;" ::: "memory");
        __syncthreads();
        if (c < 7) { ISSUE(c + 1, s ^ 1); cp_commit(); }
#pragma unroll
        for (int ks = 0; ks < 4; ks++) {
            LOADFRAG(s, ks);
#pragma unroll
            for (int mf = 0; mf < 4; mf++)
#pragma unroll
                for (int nf = 0; nf < 4; nf++)
                    MMA_F16(acc[mf][nf], af[mf], bf[nf][0], bf[nf][1]);
        }
    }

    // -------- epilogue --------
    const int cBase = bx * 128 + wn;
#pragma unroll
    for (int mf = 0; mf < 4; mf++) {
        int r = rowBase + wm + mf * 16 + grp;
#pragma unroll
        for (int nf = 0; nf < 4; nf++) {
            int c = cBase + nf * 8 + 2 * tig;
            if (FUSED) {
                epi_store(r,     c, acc[mf][nf][0], acc[mf][nf][1]);
                epi_store(r + 8, c, acc[mf][nf][2], acc[mf][nf][3]);
            } else {
                *(float2*)(Cout + (size_t)r * 512 + c) =
                    make_float2(acc[mf][nf][0], acc[mf][nf][1]);
                *(float2*)(Cout + (size_t)(r + 8) * 512 + c) =
                    make_float2(acc[mf][nf][2], acc[mf][nf][3]);
            }
        }
    }
}

// ---------------- attention: tensor-core, one warp per (b,s,h) --------------
// sim = Q K^T via m16n8k16 (Q/K fragments LDG'd straight from global: the
// d-contiguous half2 layout IS the fragment layout). Softmax on C-frags
// (4-lane shfl groups). P repacked to A-frags in registers. PV via V smem +
// trans-LDSM (round-9-validated mapping). No __syncthreads; masked warps exit.
#define SV_STRIDE 36

__global__ __launch_bounds__(128) void attn_kernel(const float* __restrict__ pos_bias)
{
    __shared__ uint32_t sV[4][32 * SV_STRIDE];

    const int tid = threadIdx.x;
    const int wid = tid >> 5, lane = tid & 31;
    const int unit = blockIdx.x * 4 + wid;     // 16384 units
    const int h = unit & 7;
    const int bs = unit >> 3;
    if (g_mask[bs >> 10]) return;              // gemm2 reads g_Vh for these

    const int r0 = bs * 32;
    const int hw = h * 32;                     // head offset in half2 words
    const int g = lane >> 2, t = lane & 3;

    // ---- stage V into per-warp smem (coalesced) ----
    uint32_t* sv = sV[wid];
#pragma unroll
    for (int it = 0; it < 8; it++) {
        int idx = lane + 32 * it;              // 256 uint4 ops
        int row = idx >> 3, w4 = (idx & 7) * 4;
        *(uint4*)&sv[row * SV_STRIDE + w4] =
            *(const uint4*)&g_Vh[(size_t)(r0 + row) * 256 + hw + w4];
    }
    __syncwarp();

    // ---- sim = Q K^T : C[mf][nf][4], kt over d (4 x k16) ----
    float C[2][4][4];
#pragma unroll
    for (int a = 0; a < 2; a++)
#pragma unroll
        for (int b = 0; b < 4; b++)
#pragma unroll
            for (int c = 0; c < 4; c++) C[a][b][c] = 0.f;

#pragma unroll
    for (int kt = 0; kt < 4; kt++) {
        uint32_t aq[2][4], bk[4][2];
#pragma unroll
        for (int mf = 0; mf < 2; mf++) {
            const uint32_t* q0 = &g_Qh[(size_t)(r0 + 16 * mf + g) * 256 + hw + 8 * kt + t];
            const uint32_t* q8 = &g_Qh[(size_t)(r0 + 16 * mf + g + 8) * 256 + hw + 8 * kt + t];
            aq[mf][0] = q0[0]; aq[mf][1] = q8[0];
            aq[mf][2] = q0[4]; aq[mf][3] = q8[4];
        }
#pragma unroll
        for (int nf = 0; nf < 4; nf++) {
            const uint32_t* kr = &g_Kh[(size_t)(r0 + 8 * nf + g) * 256 + hw + 8 * kt + t];
            bk[nf][0] = kr[0]; bk[nf][1] = kr[4];
        }
#pragma unroll
        for (int mf = 0; mf < 2; mf++)
#pragma unroll
            for (int nf = 0; nf < 4; nf++)
                MMA_F16(C[mf][nf], aq[mf], bk[nf][0], bk[nf][1]);
    }

    // ---- + pos_bias, softmax per row (rows g,g+8 per mf; 4-lane groups) ----
#pragma unroll
    for (int mf = 0; mf < 2; mf++) {
        float mA = -1e30f, mB = -1e30f;
#pragma unroll
        for (int nf = 0; nf < 4; nf++) {
            const float* pb = pos_bias + (size_t)h * 1024 + (16 * mf + g) * 32 + 8 * nf + 2 * t;
            float2 p0 = *(const float2*)pb;
            float2 p1 = *(const float2*)(pb + 8 * 32);   // row +8
            C[mf][nf][0] += p0.x; C[mf][nf][1] += p0.y;
            C[mf][nf][2] += p1.x; C[mf][nf][3] += p1.y;
            mA = fmaxf(mA, fmaxf(C[mf][nf][0], C[mf][nf][1]));
            mB = fmaxf(mB, fmaxf(C[mf][nf][2], C[mf][nf][3]));
        }
        mA = fmaxf(mA, __shfl_xor_sync(0xffffffffu, mA, 1));
        mA = fmaxf(mA, __shfl_xor_sync(0xffffffffu, mA, 2));
        mB = fmaxf(mB, __shfl_xor_sync(0xffffffffu, mB, 1));
        mB = fmaxf(mB, __shfl_xor_sync(0xffffffffu, mB, 2));
        float sA = 0.f, sB = 0.f;
#pragma unroll
        for (int nf = 0; nf < 4; nf++) {
            C[mf][nf][0] = __expf(C[mf][nf][0] - mA);
            C[mf][nf][1] = __expf(C[mf][nf][1] - mA);
            C[mf][nf][2] = __expf(C[mf][nf][2] - mB);
            C[mf][nf][3] = __expf(C[mf][nf][3] - mB);
            sA += C[mf][nf][0] + C[mf][nf][1];
            sB += C[mf][nf][2] + C[mf][nf][3];
        }
        sA += __shfl_xor_sync(0xffffffffu, sA, 1);
        sA += __shfl_xor_sync(0xffffffffu, sA, 2);
        sB += __shfl_xor_sync(0xffffffffu, sB, 1);
        sB += __shfl_xor_sync(0xffffffffu, sB, 2);
        float iA = __frcp_rn(sA), iB = __frcp_rn(sB);
#pragma unroll
        for (int nf = 0; nf < 4; nf++) {
            C[mf][nf][0] *= iA; C[mf][nf][1] *= iA;
            C[mf][nf][2] *= iB; C[mf][nf][3] *= iB;
        }
    }

    // ---- pack P into A-frags: P[kt][mf], kt over j (2 x k16) ----
    uint32_t P[2][2][4];
#pragma unroll
    for (int kt = 0; kt < 2; kt++)
#pragma unroll
        for (int mf = 0; mf < 2; mf++) {
            P[kt][mf][0] = packh2(C[mf][2 * kt][0],     C[mf][2 * kt][1]);
            P[kt][mf][1] = packh2(C[mf][2 * kt][2],     C[mf][2 * kt][3]);
            P[kt][mf][2] = packh2(C[mf][2 * kt + 1][0], C[mf][2 * kt + 1][1]);
            P[kt][mf][3] = packh2(C[mf][2 * kt + 1][2], C[mf][2 * kt + 1][3]);
        }

    // ---- PV: B-frags from V smem via trans-LDSM; 2 n-tiles per nf2 ----
    const int lrow = lane & 15, bcol8 = (lane >> 4) << 3;
    const uint32_t svb = smem_u32(sv);
#pragma unroll
    for (int nf2 = 0; nf2 < 4; nf2++) {
        uint32_t b0[4], b1[4];
        uint32_t a0 = svb + (uint32_t)((lrow)      * SV_STRIDE + ((nf2 * 16 + bcol8) >> 1)) * 4;
        uint32_t a1 = svb + (uint32_t)((16 + lrow) * SV_STRIDE + ((nf2 * 16 + bcol8) >> 1)) * 4;
        asm volatile(
            "ldmatrix.sync.aligned.m8n8.x4.trans.shared.b16 {%0,%1,%2,%3}, [%4];"
            : "=r"(b0[0]), "=r"(b0[1]), "=r"(b0[2]), "=r"(b0[3]) : "r"(a0));
        asm volatile(
            "ldmatrix.sync.aligned.m8n8.x4.trans.shared.b16 {%0,%1,%2,%3}, [%4];"
            : "=r"(b1[0]), "=r"(b1[1]), "=r"(b1[2]), "=r"(b1[3]) : "r"(a1));

        float O[2][2][4];
#pragma unroll
        for (int a = 0; a < 2; a++)
#pragma unroll
            for (int b = 0; b < 2; b++)
#pragma unroll
                for (int c = 0; c < 4; c++) O[a][b][c] = 0.f;
#pragma unroll
        for (int mf = 0; mf < 2; mf++)
#pragma unroll
            for (int nt = 0; nt < 2; nt++) {
                MMA_F16(O[mf][nt], P[0][mf], b0[2 * nt], b0[2 * nt + 1]);
                MMA_F16(O[mf][nt], P[1][mf], b1[2 * nt], b1[2 * nt + 1]);
            }
        // store: n-tile (2nf2+nt) -> d word (2nf2+nt)*4 + t
#pragma unroll
        for (int mf = 0; mf < 2; mf++)
#pragma unroll
            for (int nt = 0; nt < 2; nt++) {
                int wordc = hw + (2 * nf2 + nt) * 4 + t;
                g_AOp[(size_t)(r0 + 16 * mf + g)     * 256 + wordc] = packh2(O[mf][nt][0], O[mf][nt][1]);
                g_AOp[(size_t)(r0 + 16 * mf + g + 8) * 256 + wordc] = packh2(O[mf][nt][2], O[mf][nt][3]);
            }
    }
}

// ---------------- launch ------------------------------------------------------
// Inputs resolved by element count (robust to metadata ordering); w_q vs w_out
// (both 262144) disambiguated by position relative to w_kv.
extern "C" void kernel_launch(void* const* d_in, const int* in_sizes, int n_in,
                              void* d_out, int out_size)
{
    (void)out_size;
    int ix = -1, ipb = -1, ifoc = -1, ikv = -1, iif = -1;
    int i262[2] = {-1, -1}; int n262 = 0;
    for (int i = 0; i < n_in; i++) {
        switch (in_sizes[i]) {
            case 33554432: ix = i; break;
            case 8192:     ipb = i; break;
            case 2:        ifoc = i; break;
            case 524288:   ikv = i; break;
            case 32:       iif = i; break;
            case 262144:   if (n262 < 2) i262[n262++] = i; break;
            default: break;
        }
    }
    int iq, io;
    if (n262 == 2 && i262[0] < ikv) { iq = i262[0]; io = i262[1]; }
    else                            { io = i262[0]; iq = i262[1]; }

    const float* x        = (const float*)d_in[ix];
    const float* pos_bias = (const float*)d_in[ipb];
    const uint32_t* mask  = (const uint32_t*)d_in[ifoc];
    const float* w_q      = (const float*)d_in[iq];
    const float* w_kv     = (const float*)d_in[ikv];
    const float* w_out    = (const float*)d_in[io];
    const float* inv_freq = (const float*)d_in[iif];
    float* out = (float*)d_out;

    cudaFuncSetAttribute(gemm_kernel<1>, cudaFuncAttributeMaxDynamicSharedMemorySize, GEMM_SMEM_BYTES);
    cudaFuncSetAttribute(gemm_kernel<0>, cudaFuncAttributeMaxDynamicSharedMemorySize, GEMM_SMEM_BYTES);

    setup_kernel<<<16384 + 512 + 1, 256>>>(x, w_q, w_kv, w_out, inv_freq, mask);
    gemm_kernel<1><<<dim3(12, 512), 256, GEMM_SMEM_BYTES>>>(nullptr);
    attn_kernel<<<4096, 128>>>(pos_bias);
    gemm_kernel<0><<<dim3(4, 512), 256, GEMM_SMEM_BYTES>>>(out);
}

// round 16
// speedup vs baseline: 2.0622x; 1.3015x over previous
#include <cuda_runtime.h>
#include <cuda_fp16.h>
#include <cstdint>

// Problem dims (fixed):
//  x: (2,1024,32,512) -> M = 65536 rows of K=512
//  QKV cols = 1536 (Q 0-511, K 512-1023, V 1024-1535), out proj N=512
#define M_TOTAL 65536

// ---------------- scratch (device globals; no runtime allocation) ----------
__device__ uint32_t g_Qh[(size_t)M_TOTAL * 256];    // roped+scaled Q, half2 along d
__device__ uint32_t g_Kh[(size_t)M_TOTAL * 256];    // roped K, half2 along d
__device__ uint32_t g_Vh[(size_t)M_TOTAL * 256];    // V, half2 along d
__device__ uint32_t g_Xp[(size_t)M_TOTAL * 256];    // x as half2 pairs along k
__device__ uint32_t g_AOp[(size_t)M_TOTAL * 256];   // attn out as half2 pairs
__device__ uint32_t g_WQKVp[256 * 1536];            // [k2][n] half2(w[2k2][n], w[2k2+1][n])
__device__ uint32_t g_WOp[256 * 512];
__device__ float    g_cos[1024];
__device__ float    g_sin[1024];
__device__ int      g_mask[2];

// ---------------- helpers ----------------------------------------------------
__device__ __forceinline__ uint32_t packh2(float lo, float hi) {
    __half2 h = __floats2half2_rn(lo, hi);
    return *reinterpret_cast<uint32_t*>(&h);
}
__device__ __forceinline__ uint32_t smem_u32(const void* p) {
    uint32_t a;
    asm("{ .reg .u64 t; cvta.to.shared.u64 t, %1; cvt.u32.u64 %0, t; }"
        : "=r"(a) : "l"(p));
    return a;
}
__device__ __forceinline__ void cp16(uint32_t dst, const void* src) {
    asm volatile("cp.async.cg.shared.global [%0], [%1], 16;"
                 :: "r"(dst), "l"(src) : "memory");
}
__device__ __forceinline__ void cp_commit() {
    asm volatile("cp.async.commit_group;" ::: "memory");
}
#define MMA_F16(D, A, B0, B1)                                              \
    asm volatile(                                                          \
        "mma.sync.aligned.m16n8k16.row.col.f32.f16.f16.f32 "               \
        "{%0,%1,%2,%3}, {%4,%5,%6,%7}, {%8,%9}, {%0,%1,%2,%3};\n"          \
        : "+f"((D)[0]), "+f"((D)[1]), "+f"((D)[2]), "+f"((D)[3])           \
        : "r"((A)[0]), "r"((A)[1]), "r"((A)[2]), "r"((A)[3]),              \
          "r"(B0), "r"(B1))

// ---------------- setup: pack x/weights to fp16, rope table, mask -----------
__global__ void setup_kernel(
    const float* __restrict__ x,
    const float* __restrict__ w_q,
    const float* __restrict__ w_kv,
    const float* __restrict__ w_out,
    const float* __restrict__ inv_freq,
    const uint32_t* __restrict__ m)
{
    const int bid = blockIdx.x;
    if (bid < 16384) {
        size_t base = ((size_t)bid * 256 + threadIdx.x) * 4;
#pragma unroll
        for (int j = 0; j < 4; j++) {
            size_t w = base + j;
            float2 v = *(const float2*)(x + 2 * w);
            g_Xp[w] = packh2(v.x, v.y);
        }
    } else if (bid < 16384 + 512) {
        // weights, k-pair packed: qkv 256x1536 words, out 256x512 words
        size_t base = ((size_t)(bid - 16384) * 256 + threadIdx.x) * 4;
#pragma unroll
        for (int j = 0; j < 4; j++) {
            size_t w = base + j;
            if (w < 393216) {
                int k2 = (int)(w / 1536), n = (int)(w % 1536);
                float a, b;
                if (n < 512) {
                    a = w_q[(size_t)(2 * k2) * 512 + n];
                    b = w_q[(size_t)(2 * k2 + 1) * 512 + n];
                } else {
                    int nn = n - 512;
                    a = w_kv[(size_t)(2 * k2) * 1024 + nn];
                    b = w_kv[(size_t)(2 * k2 + 1) * 1024 + nn];
                }
                g_WQKVp[w] = packh2(a, b);
            } else {
                size_t w2 = w - 393216;
                int k2 = (int)(w2 / 512), n = (int)(w2 % 512);
                g_WOp[w2] = packh2(w_out[(size_t)(2 * k2) * 512 + n],
                                   w_out[(size_t)(2 * k2 + 1) * 512 + n]);
            }
        }
    } else {
#pragma unroll
        for (int j = 0; j < 4; j++) {
            int t = threadIdx.x * 4 + j;
            float ang = (float)(t >> 5) * inv_freq[t & 31];
            g_cos[t] = cosf(ang);
            g_sin[t] = sinf(ang);
        }
        if (threadIdx.x == 0) {
            uint32_t w0 = m[0], w1 = m[1];
            if (w0 <= 1u && w1 <= 1u) {
                g_mask[0] = (int)w0; g_mask[1] = (int)w1;
            } else {
                const unsigned char* p = (const unsigned char*)m;
                g_mask[0] = p[0] ? 1 : 0; g_mask[1] = p[1] ? 1 : 0;
            }
        }
    }
}

// Epilogue store for the fused QKV GEMM (c in [0,1536), even; v0,v1 = c,c+1).
__device__ __forceinline__ void epi_store(int r, int c, float v0, float v1) {
    int seg = c >> 9;
    int off = c & 511;
    size_t p = (size_t)r * 256 + (off >> 1);
    if (seg == 2) {
        g_Vh[p] = packh2(v0, v1);
    } else {
        int pos = r & 31;
        int fi = (c & 63) >> 1;
        float cs = g_cos[pos * 32 + fi];
        float sn = g_sin[pos * 32 + fi];
        if (seg == 0) { v0 *= 0.125f; v1 *= 0.125f; }
        uint32_t w = packh2(v0 * cs - v1 * sn, v1 * cs + v0 * sn);
        ((seg == 0) ? g_Qh : g_Kh)[p] = w;
    }
}

// ---------------- fp16 mma.sync GEMM (round-8 champion config) ---------------
// C[M,N] = A[M,512]*B[512,N]; block 128x128, BK=64 (4 k16 steps, 8 chunks),
// 8 warps (2x4), warp tile 64x32 of m16n8k16, 2-stage cp.async, A via LDSM.
#define AS_STRIDE 36
#define BS_STRIDE 136
#define AS_WORDS (128 * AS_STRIDE)   // 4608
#define BS_WORDS (32 * BS_STRIDE)    // 4352
#define STG_WORDS (AS_WORDS + BS_WORDS)
#define GEMM_SMEM_BYTES (2 * STG_WORDS * 4)

template <int FUSED>
__global__ __launch_bounds__(256, 2) void gemm_kernel(float* __restrict__ Cout)
{
    extern __shared__ uint32_t sw[];

    const int rowBase = blockIdx.y * 128;
    const int bx = blockIdx.x;

    // Masked batches: out = V exactly, so Q/K for those rows are never read.
    // gemm1 tiles bx 0-7 (Q and K columns) of masked row blocks are dead work.
    if (FUSED && bx < 8 && g_mask[rowBase >> 15]) return;

    // gemm2: masked batches have AO == V identically; attn skips them, so
    // read A from g_Vh there. Row blocks (128 rows) never straddle batches.
    const uint32_t* const Apack =
        FUSED ? g_Xp : (g_mask[rowBase >> 15] ? g_Vh : g_AOp);
    const uint32_t* const Bpack = FUSED ? g_WQKVp : g_WOp;

    const int tid = threadIdx.x;
    const int warp = tid >> 5, lane = tid & 31;
    const int wm = (warp >> 2) * 64, wn = (warp & 3) * 32;
    const int grp = lane >> 2, tig = lane & 3;
    const int ldBp = FUSED ? 1536 : 512;
    const int nb = bx * 128;
    const uint32_t sbase = smem_u32(sw);

    auto ISSUE = [&](int c, int s) {
        const uint32_t stg = sbase + (uint32_t)s * STG_WORDS * 4;
#pragma unroll
        for (int i = 0; i < 4; i++) {
            int op = tid + 256 * i;
            int row = op >> 3, c4 = (op & 7) * 4;
            cp16(stg + (uint32_t)(row * AS_STRIDE + c4) * 4,
                 Apack + (size_t)(rowBase + row) * 256 + c * 32 + c4);
        }
#pragma unroll
        for (int i = 0; i < 4; i++) {
            int op = tid + 256 * i;
            int r = op >> 5, n4 = (op & 31) * 4;
            cp16(stg + (uint32_t)(AS_WORDS + r * BS_STRIDE + n4) * 4,
                 Bpack + (size_t)(c * 32 + r) * ldBp + nb + n4);
        }
    };

    const int lrow = lane & 15, lcolA = (lane >> 4) << 2;

    uint32_t af[4][4], bf[4][2];
    auto LOADFRAG = [&](int s, int ks) {
        const int k0 = ks * 8;
        const uint32_t aBase = sbase + (uint32_t)(s * STG_WORDS) * 4;
#pragma unroll
        for (int mf = 0; mf < 4; mf++) {
            uint32_t addr = aBase + (uint32_t)((wm + mf * 16 + lrow) * AS_STRIDE + k0 + lcolA) * 4;
            asm volatile(
                "ldmatrix.sync.aligned.m8n8.x4.shared.b16 {%0,%1,%2,%3}, [%4];"
                : "=r"(af[mf][0]), "=r"(af[mf][1]), "=r"(af[mf][2]), "=r"(af[mf][3])
                : "r"(addr));
        }
        const uint32_t* bs = sw + s * STG_WORDS + AS_WORDS;
#pragma unroll
        for (int nf = 0; nf < 4; nf++) {
            int nc = wn + nf * 8 + grp;
            bf[nf][0] = bs[(k0 + tig) * BS_STRIDE + nc];
            bf[nf][1] = bs[(k0 + tig + 4) * BS_STRIDE + nc];
        }
    };

    float acc[4][4][4];
#pragma unroll
    for (int a = 0; a < 4; a++)
#pragma unroll
        for (int b = 0; b < 4; b++)
#pragma unroll
            for (int c = 0; c < 4; c++) acc[a][b][c] = 0.0f;

    ISSUE(0, 0); cp_commit();

#pragma unroll 1
    for (int c = 0; c < 8; c++) {
        const int s = c & 1;
        asm volatile("cp.async.wait_group 0;" ::: "memory");
        __syncthreads();
        if (c < 7) { ISSUE(c + 1, s ^ 1); cp_commit(); }
#pragma unroll
        for (int ks = 0; ks < 4; ks++) {
            LOADFRAG(s, ks);
#pragma unroll
            for (int mf = 0; mf < 4; mf++)
#pragma unroll
                for (int nf = 0; nf < 4; nf++)
                    MMA_F16(acc[mf][nf], af[mf], bf[nf][0], bf[nf][1]);
        }
    }

    // -------- epilogue --------
    const int cBase = bx * 128 + wn;
#pragma unroll
    for (int mf = 0; mf < 4; mf++) {
        int r = rowBase + wm + mf * 16 + grp;
#pragma unroll
        for (int nf = 0; nf < 4; nf++) {
            int c = cBase + nf * 8 + 2 * tig;
            if (FUSED) {
                epi_store(r,     c, acc[mf][nf][0], acc[mf][nf][1]);
                epi_store(r + 8, c, acc[mf][nf][2], acc[mf][nf][3]);
            } else {
                *(float2*)(Cout + (size_t)r * 512 + c) =
                    make_float2(acc[mf][nf][0], acc[mf][nf][1]);
                *(float2*)(Cout + (size_t)(r + 8) * 512 + c) =
                    make_float2(acc[mf][nf][2], acc[mf][nf][3]);
            }
        }
    }
}

// ---------------- attention: tensor-core, one warp per (b,s,h) --------------
// sim = Q K^T via m16n8k16 (Q/K fragments LDG'd straight from global: the
// d-contiguous half2 layout IS the fragment layout). Softmax on C-frags
// (4-lane shfl groups). P repacked to A-frags in registers. PV via V smem +
// trans-LDSM. No __syncthreads; masked warps exit.
#define SV_STRIDE 36

__global__ __launch_bounds__(128) void attn_kernel(const float* __restrict__ pos_bias)
{
    __shared__ uint32_t sV[4][32 * SV_STRIDE];

    const int tid = threadIdx.x;
    const int wid = tid >> 5, lane = tid & 31;
    const int unit = blockIdx.x * 4 + wid;     // 16384 units
    const int h = unit & 7;
    const int bs = unit >> 3;
    if (g_mask[bs >> 10]) return;              // gemm2 reads g_Vh for these

    const int r0 = bs * 32;
    const int hw = h * 32;                     // head offset in half2 words
    const int g = lane >> 2, t = lane & 3;

    // ---- stage V into per-warp smem (coalesced) ----
    uint32_t* sv = sV[wid];
#pragma unroll
    for (int it = 0; it < 8; it++) {
        int idx = lane + 32 * it;              // 256 uint4 ops
        int row = idx >> 3, w4 = (idx & 7) * 4;
        *(uint4*)&sv[row * SV_STRIDE + w4] =
            *(const uint4*)&g_Vh[(size_t)(r0 + row) * 256 + hw + w4];
    }
    __syncwarp();

    // ---- sim = Q K^T : C[mf][nf][4], kt over d (4 x k16) ----
    float C[2][4][4];
#pragma unroll
    for (int a = 0; a < 2; a++)
#pragma unroll
        for (int b = 0; b < 4; b++)
#pragma unroll
            for (int c = 0; c < 4; c++) C[a][b][c] = 0.f;

#pragma unroll
    for (int kt = 0; kt < 4; kt++) {
        uint32_t aq[2][4], bk[4][2];
#pragma unroll
        for (int mf = 0; mf < 2; mf++) {
            const uint32_t* q0 = &g_Qh[(size_t)(r0 + 16 * mf + g) * 256 + hw + 8 * kt + t];
            const uint32_t* q8 = &g_Qh[(size_t)(r0 + 16 * mf + g + 8) * 256 + hw + 8 * kt + t];
            aq[mf][0] = q0[0]; aq[mf][1] = q8[0];
            aq[mf][2] = q0[4]; aq[mf][3] = q8[4];
        }
#pragma unroll
        for (int nf = 0; nf < 4; nf++) {
            const uint32_t* kr = &g_Kh[(size_t)(r0 + 8 * nf + g) * 256 + hw + 8 * kt + t];
            bk[nf][0] = kr[0]; bk[nf][1] = kr[4];
        }
#pragma unroll
        for (int mf = 0; mf < 2; mf++)
#pragma unroll
            for (int nf = 0; nf < 4; nf++)
                MMA_F16(C[mf][nf], aq[mf], bk[nf][0], bk[nf][1]);
    }

    // ---- + pos_bias, softmax per row (rows g,g+8 per mf; 4-lane groups) ----
#pragma unroll
    for (int mf = 0; mf < 2; mf++) {
        float mA = -1e30f, mB = -1e30f;
#pragma unroll
        for (int nf = 0; nf < 4; nf++) {
            const float* pb = pos_bias + (size_t)h * 1024 + (16 * mf + g) * 32 + 8 * nf + 2 * t;
            float2 p0 = *(const float2*)pb;
            float2 p1 = *(const float2*)(pb + 8 * 32);   // row +8
            C[mf][nf][0] += p0.x; C[mf][nf][1] += p0.y;
            C[mf][nf][2] += p1.x; C[mf][nf][3] += p1.y;
            mA = fmaxf(mA, fmaxf(C[mf][nf][0], C[mf][nf][1]));
            mB = fmaxf(mB, fmaxf(C[mf][nf][2], C[mf][nf][3]));
        }
        mA = fmaxf(mA, __shfl_xor_sync(0xffffffffu, mA, 1));
        mA = fmaxf(mA, __shfl_xor_sync(0xffffffffu, mA, 2));
        mB = fmaxf(mB, __shfl_xor_sync(0xffffffffu, mB, 1));
        mB = fmaxf(mB, __shfl_xor_sync(0xffffffffu, mB, 2));
        float sA = 0.f, sB = 0.f;
#pragma unroll
        for (int nf = 0; nf < 4; nf++) {
            C[mf][nf][0] = __expf(C[mf][nf][0] - mA);
            C[mf][nf][1] = __expf(C[mf][nf][1] - mA);
            C[mf][nf][2] = __expf(C[mf][nf][2] - mB);
            C[mf][nf][3] = __expf(C[mf][nf][3] - mB);
            sA += C[mf][nf][0] + C[mf][nf][1];
            sB += C[mf][nf][2] + C[mf][nf][3];
        }
        sA += __shfl_xor_sync(0xffffffffu, sA, 1);
        sA += __shfl_xor_sync(0xffffffffu, sA, 2);
        sB += __shfl_xor_sync(0xffffffffu, sB, 1);
        sB += __shfl_xor_sync(0xffffffffu, sB, 2);
        float iA = __frcp_rn(sA), iB = __frcp_rn(sB);
#pragma unroll
        for (int nf = 0; nf < 4; nf++) {
            C[mf][nf][0] *= iA; C[mf][nf][1] *= iA;
            C[mf][nf][2] *= iB; C[mf][nf][3] *= iB;
        }
    }

    // ---- pack P into A-frags: P[kt][mf], kt over j (2 x k16) ----
    uint32_t P[2][2][4];
#pragma unroll
    for (int kt = 0; kt < 2; kt++)
#pragma unroll
        for (int mf = 0; mf < 2; mf++) {
            P[kt][mf][0] = packh2(C[mf][2 * kt][0],     C[mf][2 * kt][1]);
            P[kt][mf][1] = packh2(C[mf][2 * kt][2],     C[mf][2 * kt][3]);
            P[kt][mf][2] = packh2(C[mf][2 * kt + 1][0], C[mf][2 * kt + 1][1]);
            P[kt][mf][3] = packh2(C[mf][2 * kt + 1][2], C[mf][2 * kt + 1][3]);
        }

    // ---- PV: B-frags from V smem via trans-LDSM; 2 n-tiles per nf2 ----
    const int lrow = lane & 15, bcol8 = (lane >> 4) << 3;
    const uint32_t svb = smem_u32(sv);
#pragma unroll
    for (int nf2 = 0; nf2 < 4; nf2++) {
        uint32_t b0[4], b1[4];
        uint32_t a0 = svb + (uint32_t)((lrow)      * SV_STRIDE + ((nf2 * 16 + bcol8) >> 1)) * 4;
        uint32_t a1 = svb + (uint32_t)((16 + lrow) * SV_STRIDE + ((nf2 * 16 + bcol8) >> 1)) * 4;
        asm volatile(
            "ldmatrix.sync.aligned.m8n8.x4.trans.shared.b16 {%0,%1,%2,%3}, [%4];"
            : "=r"(b0[0]), "=r"(b0[1]), "=r"(b0[2]), "=r"(b0[3]) : "r"(a0));
        asm volatile(
            "ldmatrix.sync.aligned.m8n8.x4.trans.shared.b16 {%0,%1,%2,%3}, [%4];"
            : "=r"(b1[0]), "=r"(b1[1]), "=r"(b1[2]), "=r"(b1[3]) : "r"(a1));

        float O[2][2][4];
#pragma unroll
        for (int a = 0; a < 2; a++)
#pragma unroll
            for (int b = 0; b < 2; b++)
#pragma unroll
                for (int c = 0; c < 4; c++) O[a][b][c] = 0.f;
#pragma unroll
        for (int mf = 0; mf < 2; mf++)
#pragma unroll
            for (int nt = 0; nt < 2; nt++) {
                MMA_F16(O[mf][nt], P[0][mf], b0[2 * nt], b0[2 * nt + 1]);
                MMA_F16(O[mf][nt], P[1][mf], b1[2 * nt], b1[2 * nt + 1]);
            }
        // store: n-tile (2nf2+nt) -> d word (2nf2+nt)*4 + t
#pragma unroll
        for (int mf = 0; mf < 2; mf++)
#pragma unroll
            for (int nt = 0; nt < 2; nt++) {
                int wordc = hw + (2 * nf2 + nt) * 4 + t;
                g_AOp[(size_t)(r0 + 16 * mf + g)     * 256 + wordc] = packh2(O[mf][nt][0], O[mf][nt][1]);
                g_AOp[(size_t)(r0 + 16 * mf + g + 8) * 256 + wordc] = packh2(O[mf][nt][2], O[mf][nt][3]);
            }
    }
}

// ---------------- launch ------------------------------------------------------
// Inputs resolved by element count (robust to metadata ordering); w_q vs w_out
// (both 262144) disambiguated by position relative to w_kv.
extern "C" void kernel_launch(void* const* d_in, const int* in_sizes, int n_in,
                              void* d_out, int out_size)
{
    (void)out_size;
    int ix = -1, ipb = -1, ifoc = -1, ikv = -1, iif = -1;
    int i262[2] = {-1, -1}; int n262 = 0;
    for (int i = 0; i < n_in; i++) {
        switch (in_sizes[i]) {
            case 33554432: ix = i; break;
            case 8192:     ipb = i; break;
            case 2:        ifoc = i; break;
            case 524288:   ikv = i; break;
            case 32:       iif = i; break;
            case 262144:   if (n262 < 2) i262[n262++] = i; break;
            default: break;
        }
    }
    int iq, io;
    if (n262 == 2 && i262[0] < ikv) { iq = i262[0]; io = i262[1]; }
    else                            { io = i262[0]; iq = i262[1]; }

    const float* x        = (const float*)d_in[ix];
    const float* pos_bias = (const float*)d_in[ipb];
    const uint32_t* mask  = (const uint32_t*)d_in[ifoc];
    const float* w_q      = (const float*)d_in[iq];
    const float* w_kv     = (const float*)d_in[ikv];
    const float* w_out    = (const float*)d_in[io];
    const float* inv_freq = (const float*)d_in[iif];
    float* out = (float*)d_out;

    cudaFuncSetAttribute(gemm_kernel<1>, cudaFuncAttributeMaxDynamicSharedMemorySize, GEMM_SMEM_BYTES);
    cudaFuncSetAttribute(gemm_kernel<0>, cudaFuncAttributeMaxDynamicSharedMemorySize, GEMM_SMEM_BYTES);

    setup_kernel<<<16384 + 512 + 1, 256>>>(x, w_q, w_kv, w_out, inv_freq, mask);
    gemm_kernel<1><<<dim3(12, 512), 256, GEMM_SMEM_BYTES>>>(nullptr);
    attn_kernel<<<4096, 128>>>(pos_bias);
    gemm_kernel<0><<<dim3(4, 512), 256, GEMM_SMEM_BYTES>>>(out);
}

// round 17
// speedup vs baseline: 2.2492x; 1.0907x over previous
#include <cuda_runtime.h>
#include <cuda_fp16.h>
#include <cstdint>

// Problem dims (fixed):
//  x: (2,1024,32,512) -> M = 65536 rows of K=512
//  QKV cols = 1536 (Q 0-511, K 512-1023, V 1024-1535), out proj N=512
#define M_TOTAL 65536

// ---------------- scratch (device globals; no runtime allocation) ----------
__device__ uint32_t g_Qh[(size_t)M_TOTAL * 256];    // roped+scaled Q, half2 along d
__device__ uint32_t g_Kh[(size_t)M_TOTAL * 256];    // roped K, half2 along d
__device__ uint32_t g_Vh[(size_t)M_TOTAL * 256];    // V, half2 along d
__device__ uint32_t g_Xp[(size_t)M_TOTAL * 256];    // x as half2 pairs along k
__device__ uint32_t g_AOp[(size_t)M_TOTAL * 256];   // attn out as half2 pairs
__device__ uint32_t g_WQKVp[256 * 1536];            // [k2][n] half2(w[2k2][n], w[2k2+1][n])
__device__ uint32_t g_WOp[256 * 512];
__device__ uint32_t g_WVp[512 * 256];               // w_v rows, k-pair packed (A for W')
__device__ float    g_Wtmp[512 * 512];              // W' = w_v @ w_out, fp32
__device__ uint32_t g_Wpp[256 * 512];               // W' k-pair packed (B for masked gemm2)
__device__ float    g_cos[1024];
__device__ float    g_sin[1024];
__device__ int      g_mask[2];

// ---------------- helpers ----------------------------------------------------
__device__ __forceinline__ uint32_t packh2(float lo, float hi) {
    __half2 h = __floats2half2_rn(lo, hi);
    return *reinterpret_cast<uint32_t*>(&h);
}
__device__ __forceinline__ uint32_t smem_u32(const void* p) {
    uint32_t a;
    asm("{ .reg .u64 t; cvta.to.shared.u64 t, %1; cvt.u32.u64 %0, t; }"
        : "=r"(a) : "l"(p));
    return a;
}
__device__ __forceinline__ void cp16(uint32_t dst, const void* src) {
    asm volatile("cp.async.cg.shared.global [%0], [%1], 16;"
                 :: "r"(dst), "l"(src) : "memory");
}
__device__ __forceinline__ void cp_commit() {
    asm volatile("cp.async.commit_group;" ::: "memory");
}
#define MMA_F16(D, A, B0, B1)                                              \
    asm volatile(                                                          \
        "mma.sync.aligned.m16n8k16.row.col.f32.f16.f16.f32 "               \
        "{%0,%1,%2,%3}, {%4,%5,%6,%7}, {%8,%9}, {%0,%1,%2,%3};\n"          \
        : "+f"((D)[0]), "+f"((D)[1]), "+f"((D)[2]), "+f"((D)[3])           \
        : "r"((A)[0]), "r"((A)[1]), "r"((A)[2]), "r"((A)[3]),              \
          "r"(B0), "r"(B1))

// ---------------- setup: pack x/weights to fp16, rope table, mask -----------
// grid: [0,16384) x-pack | [16384,16896) weights | 16896 rope+mask |
//       [16897,17025) w_v A-pack for W'
__global__ void setup_kernel(
    const float* __restrict__ x,
    const float* __restrict__ w_q,
    const float* __restrict__ w_kv,
    const float* __restrict__ w_out,
    const float* __restrict__ inv_freq,
    const uint32_t* __restrict__ m)
{
    const int bid = blockIdx.x;
    if (bid < 16384) {
        size_t base = ((size_t)bid * 256 + threadIdx.x) * 4;
        float4 a = *(const float4*)(x + 2 * base);
        float4 b = *(const float4*)(x + 2 * base + 4);
        *(uint4*)&g_Xp[base] = make_uint4(packh2(a.x, a.y), packh2(a.z, a.w),
                                          packh2(b.x, b.y), packh2(b.z, b.w));
    } else if (bid < 16384 + 512) {
        // weights, k-pair packed: qkv 256x1536 words, out 256x512 words
        size_t base = ((size_t)(bid - 16384) * 256 + threadIdx.x) * 4;
#pragma unroll
        for (int j = 0; j < 4; j++) {
            size_t w = base + j;
            if (w < 393216) {
                int k2 = (int)(w / 1536), n = (int)(w % 1536);
                float a, b;
                if (n < 512) {
                    a = w_q[(size_t)(2 * k2) * 512 + n];
                    b = w_q[(size_t)(2 * k2 + 1) * 512 + n];
                } else {
                    int nn = n - 512;
                    a = w_kv[(size_t)(2 * k2) * 1024 + nn];
                    b = w_kv[(size_t)(2 * k2 + 1) * 1024 + nn];
                }
                g_WQKVp[w] = packh2(a, b);
            } else {
                size_t w2 = w - 393216;
                int k2 = (int)(w2 / 512), n = (int)(w2 % 512);
                g_WOp[w2] = packh2(w_out[(size_t)(2 * k2) * 512 + n],
                                   w_out[(size_t)(2 * k2 + 1) * 512 + n]);
            }
        }
    } else if (bid == 16384 + 512) {
#pragma unroll
        for (int j = 0; j < 4; j++) {
            int t = threadIdx.x * 4 + j;
            float ang = (float)(t >> 5) * inv_freq[t & 31];
            g_cos[t] = cosf(ang);
            g_sin[t] = sinf(ang);
        }
        if (threadIdx.x == 0) {
            uint32_t w0 = m[0], w1 = m[1];
            if (w0 <= 1u && w1 <= 1u) {
                g_mask[0] = (int)w0; g_mask[1] = (int)w1;
            } else {
                const unsigned char* p = (const unsigned char*)m;
                g_mask[0] = p[0] ? 1 : 0; g_mask[1] = p[1] ? 1 : 0;
            }
        }
    } else {
        // w_v A-pack: g_WVp[i*256 + j2] = half2(w_v[i][2j2], w_v[i][2j2+1]),
        // w_v[i][j] = w_kv[i*1024 + 512 + j]; 8 consecutive floats per thread.
        int w = (bid - 16897) * 1024 + threadIdx.x * 4;   // 131072 words
        int i = w >> 8, j2 = w & 255;
        const float* src = w_kv + (size_t)i * 1024 + 512 + 2 * j2;
        float4 a = *(const float4*)src;
        float4 b = *(const float4*)(src + 4);
        *(uint4*)&g_WVp[w] = make_uint4(packh2(a.x, a.y), packh2(a.z, a.w),
                                        packh2(b.x, b.y), packh2(b.z, b.w));
    }
}

// Repack W' fp32 -> k-pair fp16 [k2][n]
__global__ void wpack_kernel() {
    int w = blockIdx.x * 256 + threadIdx.x;     // 131072 words
    int k2 = w >> 9, n = w & 511;
    g_Wpp[w] = packh2(g_Wtmp[(size_t)(2 * k2) * 512 + n],
                      g_Wtmp[(size_t)(2 * k2 + 1) * 512 + n]);
}

// Epilogue store for the fused QKV GEMM (c in [0,1536), even; v0,v1 = c,c+1).
__device__ __forceinline__ void epi_store(int r, int c, float v0, float v1) {
    int seg = c >> 9;
    int off = c & 511;
    size_t p = (size_t)r * 256 + (off >> 1);
    if (seg == 2) {
        g_Vh[p] = packh2(v0, v1);
    } else {
        int pos = r & 31;
        int fi = (c & 63) >> 1;
        float cs = g_cos[pos * 32 + fi];
        float sn = g_sin[pos * 32 + fi];
        if (seg == 0) { v0 *= 0.125f; v1 *= 0.125f; }
        uint32_t w = packh2(v0 * cs - v1 * sn, v1 * cs + v0 * sn);
        ((seg == 0) ? g_Qh : g_Kh)[p] = w;
    }
}

// ---------------- fp16 mma.sync GEMM (round-8 champion config) ---------------
// MODE 1: QKV (A=g_Xp, B=g_WQKVp, rope epilogue; masked row blocks fully skip)
// MODE 2: W' = w_v @ w_out (A=g_WVp, B=g_WOp, fp32 store to g_Wtmp; grid 4x4)
// MODE 0: out-proj (masked rows: A=g_Xp, B=g_Wpp; else A=g_AOp, B=g_WOp)
#define AS_STRIDE 36
#define BS_STRIDE 136
#define AS_WORDS (128 * AS_STRIDE)   // 4608
#define BS_WORDS (32 * BS_STRIDE)    // 4352
#define STG_WORDS (AS_WORDS + BS_WORDS)
#define GEMM_SMEM_BYTES (2 * STG_WORDS * 4)

template <int MODE>
__global__ __launch_bounds__(256, 2) void gemm_kernel(float* __restrict__ Cout)
{
    extern __shared__ uint32_t sw[];

    const int rowBase = blockIdx.y * 128;
    const int bx = blockIdx.x;

    // Masked batches: out = x @ W' handled entirely in MODE 0 -> all QKV work
    // for those rows is dead.
    if (MODE == 1 && g_mask[rowBase >> 15]) return;

    const bool msk = (MODE == 0) && g_mask[rowBase >> 15];
    const uint32_t* const Apack =
        (MODE == 1) ? g_Xp : (MODE == 2) ? g_WVp : (msk ? g_Xp : g_AOp);
    const uint32_t* const Bpack =
        (MODE == 1) ? g_WQKVp : (MODE == 2) ? g_WOp : (msk ? g_Wpp : g_WOp);
    const int ldBp = (MODE == 1) ? 1536 : 512;

    const int tid = threadIdx.x;
    const int warp = tid >> 5, lane = tid & 31;
    const int wm = (warp >> 2) * 64, wn = (warp & 3) * 32;
    const int grp = lane >> 2, tig = lane & 3;
    const int nb = bx * 128;
    const uint32_t sbase = smem_u32(sw);

    auto ISSUE = [&](int c, int s) {
        const uint32_t stg = sbase + (uint32_t)s * STG_WORDS * 4;
#pragma unroll
        for (int i = 0; i < 4; i++) {
            int op = tid + 256 * i;
            int row = op >> 3, c4 = (op & 7) * 4;
            cp16(stg + (uint32_t)(row * AS_STRIDE + c4) * 4,
                 Apack + (size_t)(rowBase + row) * 256 + c * 32 + c4);
        }
#pragma unroll
        for (int i = 0; i < 4; i++) {
            int op = tid + 256 * i;
            int r = op >> 5, n4 = (op & 31) * 4;
            cp16(stg + (uint32_t)(AS_WORDS + r * BS_STRIDE + n4) * 4,
                 Bpack + (size_t)(c * 32 + r) * ldBp + nb + n4);
        }
    };

    const int lrow = lane & 15, lcolA = (lane >> 4) << 2;

    uint32_t af[4][4], bf[4][2];
    auto LOADFRAG = [&](int s, int ks) {
        const int k0 = ks * 8;
        const uint32_t aBase = sbase + (uint32_t)(s * STG_WORDS) * 4;
#pragma unroll
        for (int mf = 0; mf < 4; mf++) {
            uint32_t addr = aBase + (uint32_t)((wm + mf * 16 + lrow) * AS_STRIDE + k0 + lcolA) * 4;
            asm volatile(
                "ldmatrix.sync.aligned.m8n8.x4.shared.b16 {%0,%1,%2,%3}, [%4];"
                : "=r"(af[mf][0]), "=r"(af[mf][1]), "=r"(af[mf][2]), "=r"(af[mf][3])
                : "r"(addr));
        }
        const uint32_t* bs = sw + s * STG_WORDS + AS_WORDS;
#pragma unroll
        for (int nf = 0; nf < 4; nf++) {
            int nc = wn + nf * 8 + grp;
            bf[nf][0] = bs[(k0 + tig) * BS_STRIDE + nc];
            bf[nf][1] = bs[(k0 + tig + 4) * BS_STRIDE + nc];
        }
    };

    float acc[4][4][4];
#pragma unroll
    for (int a = 0; a < 4; a++)
#pragma unroll
        for (int b = 0; b < 4; b++)
#pragma unroll
            for (int c = 0; c < 4; c++) acc[a][b][c] = 0.0f;

    ISSUE(0, 0); cp_commit();

#pragma unroll 1
    for (int c = 0; c < 8; c++) {
        const int s = c & 1;
        asm volatile("cp.async.wait_group 0;" ::: "memory");
        __syncthreads();
        if (c < 7) { ISSUE(c + 1, s ^ 1); cp_commit(); }
#pragma unroll
        for (int ks = 0; ks < 4; ks++) {
            LOADFRAG(s, ks);
#pragma unroll
            for (int mf = 0; mf < 4; mf++)
#pragma unroll
                for (int nf = 0; nf < 4; nf++)
                    MMA_F16(acc[mf][nf], af[mf], bf[nf][0], bf[nf][1]);
        }
    }

    // -------- epilogue --------
    const int cBase = bx * 128 + wn;
#pragma unroll
    for (int mf = 0; mf < 4; mf++) {
        int r = rowBase + wm + mf * 16 + grp;
#pragma unroll
        for (int nf = 0; nf < 4; nf++) {
            int c = cBase + nf * 8 + 2 * tig;
            if (MODE == 1) {
                epi_store(r,     c, acc[mf][nf][0], acc[mf][nf][1]);
                epi_store(r + 8, c, acc[mf][nf][2], acc[mf][nf][3]);
            } else if (MODE == 2) {
                *(float2*)(g_Wtmp + (size_t)r * 512 + c) =
                    make_float2(acc[mf][nf][0], acc[mf][nf][1]);
                *(float2*)(g_Wtmp + (size_t)(r + 8) * 512 + c) =
                    make_float2(acc[mf][nf][2], acc[mf][nf][3]);
            } else {
                *(float2*)(Cout + (size_t)r * 512 + c) =
                    make_float2(acc[mf][nf][0], acc[mf][nf][1]);
                *(float2*)(Cout + (size_t)(r + 8) * 512 + c) =
                    make_float2(acc[mf][nf][2], acc[mf][nf][3]);
            }
        }
    }
}

// ---------------- attention: tensor-core, one warp per (b,s,h) --------------
// sim = Q K^T via m16n8k16 (Q/K fragments LDG'd straight from global: the
// d-contiguous half2 layout IS the fragment layout). Softmax on C-frags
// (4-lane shfl groups). P repacked to A-frags in registers. PV via V smem +
// trans-LDSM. No __syncthreads; masked warps exit.
#define SV_STRIDE 36

__global__ __launch_bounds__(128) void attn_kernel(const float* __restrict__ pos_bias)
{
    __shared__ uint32_t sV[4][32 * SV_STRIDE];

    const int tid = threadIdx.x;
    const int wid = tid >> 5, lane = tid & 31;
    const int unit = blockIdx.x * 4 + wid;     // 16384 units
    const int h = unit & 7;
    const int bs = unit >> 3;
    if (g_mask[bs >> 10]) return;              // masked rows: out = x @ W'

    const int r0 = bs * 32;
    const int hw = h * 32;                     // head offset in half2 words
    const int g = lane >> 2, t = lane & 3;

    // ---- stage V into per-warp smem (coalesced) ----
    uint32_t* sv = sV[wid];
#pragma unroll
    for (int it = 0; it < 8; it++) {
        int idx = lane + 32 * it;              // 256 uint4 ops
        int row = idx >> 3, w4 = (idx & 7) * 4;
        *(uint4*)&sv[row * SV_STRIDE + w4] =
            *(const uint4*)&g_Vh[(size_t)(r0 + row) * 256 + hw + w4];
    }
    __syncwarp();

    // ---- sim = Q K^T : C[mf][nf][4], kt over d (4 x k16) ----
    float C[2][4][4];
#pragma unroll
    for (int a = 0; a < 2; a++)
#pragma unroll
        for (int b = 0; b < 4; b++)
#pragma unroll
            for (int c = 0; c < 4; c++) C[a][b][c] = 0.f;

#pragma unroll
    for (int kt = 0; kt < 4; kt++) {
        uint32_t aq[2][4], bk[4][2];
#pragma unroll
        for (int mf = 0; mf < 2; mf++) {
            const uint32_t* q0 = &g_Qh[(size_t)(r0 + 16 * mf + g) * 256 + hw + 8 * kt + t];
            const uint32_t* q8 = &g_Qh[(size_t)(r0 + 16 * mf + g + 8) * 256 + hw + 8 * kt + t];
            aq[mf][0] = q0[0]; aq[mf][1] = q8[0];
            aq[mf][2] = q0[4]; aq[mf][3] = q8[4];
        }
#pragma unroll
        for (int nf = 0; nf < 4; nf++) {
            const uint32_t* kr = &g_Kh[(size_t)(r0 + 8 * nf + g) * 256 + hw + 8 * kt + t];
            bk[nf][0] = kr[0]; bk[nf][1] = kr[4];
        }
#pragma unroll
        for (int mf = 0; mf < 2; mf++)
#pragma unroll
            for (int nf = 0; nf < 4; nf++)
                MMA_F16(C[mf][nf], aq[mf], bk[nf][0], bk[nf][1]);
    }

    // ---- + pos_bias, softmax per row (rows g,g+8 per mf; 4-lane groups) ----
#pragma unroll
    for (int mf = 0; mf < 2; mf++) {
        float mA = -1e30f, mB = -1e30f;
#pragma unroll
        for (int nf = 0; nf < 4; nf++) {
            const float* pb = pos_bias + (size_t)h * 1024 + (16 * mf + g) * 32 + 8 * nf + 2 * t;
            float2 p0 = *(const float2*)pb;
            float2 p1 = *(const float2*)(pb + 8 * 32);   // row +8
            C[mf][nf][0] += p0.x; C[mf][nf][1] += p0.y;
            C[mf][nf][2] += p1.x; C[mf][nf][3] += p1.y;
            mA = fmaxf(mA, fmaxf(C[mf][nf][0], C[mf][nf][1]));
            mB = fmaxf(mB, fmaxf(C[mf][nf][2], C[mf][nf][3]));
        }
        mA = fmaxf(mA, __shfl_xor_sync(0xffffffffu, mA, 1));
        mA = fmaxf(mA, __shfl_xor_sync(0xffffffffu, mA, 2));
        mB = fmaxf(mB, __shfl_xor_sync(0xffffffffu, mB, 1));
        mB = fmaxf(mB, __shfl_xor_sync(0xffffffffu, mB, 2));
        float sA = 0.f, sB = 0.f;
#pragma unroll
        for (int nf = 0; nf < 4; nf++) {
            C[mf][nf][0] = __expf(C[mf][nf][0] - mA);
            C[mf][nf][1] = __expf(C[mf][nf][1] - mA);
            C[mf][nf][2] = __expf(C[mf][nf][2] - mB);
            C[mf][nf][3] = __expf(C[mf][nf][3] - mB);
            sA += C[mf][nf][0] + C[mf][nf][1];
            sB += C[mf][nf][2] + C[mf][nf][3];
        }
        sA += __shfl_xor_sync(0xffffffffu, sA, 1);
        sA += __shfl_xor_sync(0xffffffffu, sA, 2);
        sB += __shfl_xor_sync(0xffffffffu, sB, 1);
        sB += __shfl_xor_sync(0xffffffffu, sB, 2);
        float iA = __frcp_rn(sA), iB = __frcp_rn(sB);
#pragma unroll
        for (int nf = 0; nf < 4; nf++) {
            C[mf][nf][0] *= iA; C[mf][nf][1] *= iA;
            C[mf][nf][2] *= iB; C[mf][nf][3] *= iB;
        }
    }

    // ---- pack P into A-frags: P[kt][mf], kt over j (2 x k16) ----
    uint32_t P[2][2][4];
#pragma unroll
    for (int kt = 0; kt < 2; kt++)
#pragma unroll
        for (int mf = 0; mf < 2; mf++) {
            P[kt][mf][0] = packh2(C[mf][2 * kt][0],     C[mf][2 * kt][1]);
            P[kt][mf][1] = packh2(C[mf][2 * kt][2],     C[mf][2 * kt][3]);
            P[kt][mf][2] = packh2(C[mf][2 * kt + 1][0], C[mf][2 * kt + 1][1]);
            P[kt][mf][3] = packh2(C[mf][2 * kt + 1][2], C[mf][2 * kt + 1][3]);
        }

    // ---- PV: B-frags from V smem via trans-LDSM; 2 n-tiles per nf2 ----
    const int lrow = lane & 15, bcol8 = (lane >> 4) << 3;
    const uint32_t svb = smem_u32(sv);
#pragma unroll
    for (int nf2 = 0; nf2 < 4; nf2++) {
        uint32_t b0[4], b1[4];
        uint32_t a0 = svb + (uint32_t)((lrow)      * SV_STRIDE + ((nf2 * 16 + bcol8) >> 1)) * 4;
        uint32_t a1 = svb + (uint32_t)((16 + lrow) * SV_STRIDE + ((nf2 * 16 + bcol8) >> 1)) * 4;
        asm volatile(
            "ldmatrix.sync.aligned.m8n8.x4.trans.shared.b16 {%0,%1,%2,%3}, [%4];"
            : "=r"(b0[0]), "=r"(b0[1]), "=r"(b0[2]), "=r"(b0[3]) : "r"(a0));
        asm volatile(
            "ldmatrix.sync.aligned.m8n8.x4.trans.shared.b16 {%0,%1,%2,%3}, [%4];"
            : "=r"(b1[0]), "=r"(b1[1]), "=r"(b1[2]), "=r"(b1[3]) : "r"(a1));

        float O[2][2][4];
#pragma unroll
        for (int a = 0; a < 2; a++)
#pragma unroll
            for (int b = 0; b < 2; b++)
#pragma unroll
                for (int c = 0; c < 4; c++) O[a][b][c] = 0.f;
#pragma unroll
        for (int mf = 0; mf < 2; mf++)
#pragma unroll
            for (int nt = 0; nt < 2; nt++) {
                MMA_F16(O[mf][nt], P[0][mf], b0[2 * nt], b0[2 * nt + 1]);
                MMA_F16(O[mf][nt], P[1][mf], b1[2 * nt], b1[2 * nt + 1]);
            }
        // store: n-tile (2nf2+nt) -> d word (2nf2+nt)*4 + t
#pragma unroll
        for (int mf = 0; mf < 2; mf++)
#pragma unroll
            for (int nt = 0; nt < 2; nt++) {
                int wordc = hw + (2 * nf2 + nt) * 4 + t;
                g_AOp[(size_t)(r0 + 16 * mf + g)     * 256 + wordc] = packh2(O[mf][nt][0], O[mf][nt][1]);
                g_AOp[(size_t)(r0 + 16 * mf + g + 8) * 256 + wordc] = packh2(O[mf][nt][2], O[mf][nt][3]);
            }
    }
}

// ---------------- launch ------------------------------------------------------
// Inputs resolved by element count (robust to metadata ordering); w_q vs w_out
// (both 262144) disambiguated by position relative to w_kv.
extern "C" void kernel_launch(void* const* d_in, const int* in_sizes, int n_in,
                              void* d_out, int out_size)
{
    (void)out_size;
    int ix = -1, ipb = -1, ifoc = -1, ikv = -1, iif = -1;
    int i262[2] = {-1, -1}; int n262 = 0;
    for (int i = 0; i < n_in; i++) {
        switch (in_sizes[i]) {
            case 33554432: ix = i; break;
            case 8192:     ipb = i; break;
            case 2:        ifoc = i; break;
            case 524288:   ikv = i; break;
            case 32:       iif = i; break;
            case 262144:   if (n262 < 2) i262[n262++] = i; break;
            default: break;
        }
    }
    int iq, io;
    if (n262 == 2 && i262[0] < ikv) { iq = i262[0]; io = i262[1]; }
    else                            { io = i262[0]; iq = i262[1]; }

    const float* x        = (const float*)d_in[ix];
    const float* pos_bias = (const float*)d_in[ipb];
    const uint32_t* mask  = (const uint32_t*)d_in[ifoc];
    const float* w_q      = (const float*)d_in[iq];
    const float* w_kv     = (const float*)d_in[ikv];
    const float* w_out    = (const float*)d_in[io];
    const float* inv_freq = (const float*)d_in[iif];
    float* out = (float*)d_out;

    cudaFuncSetAttribute(gemm_kernel<0>, cudaFuncAttributeMaxDynamicSharedMemorySize, GEMM_SMEM_BYTES);
    cudaFuncSetAttribute(gemm_kernel<1>, cudaFuncAttributeMaxDynamicSharedMemorySize, GEMM_SMEM_BYTES);
    cudaFuncSetAttribute(gemm_kernel<2>, cudaFuncAttributeMaxDynamicSharedMemorySize, GEMM_SMEM_BYTES);

    setup_kernel<<<16384 + 512 + 1 + 128, 256>>>(x, w_q, w_kv, w_out, inv_freq, mask);
    gemm_kernel<1><<<dim3(12, 512), 256, GEMM_SMEM_BYTES>>>(nullptr);   // QKV (unmasked rows)
    gemm_kernel<2><<<dim3(4, 4), 256, GEMM_SMEM_BYTES>>>(nullptr);      // W' = w_v @ w_out
    wpack_kernel<<<512, 256>>>();
    attn_kernel<<<4096, 128>>>(pos_bias);
    gemm_kernel<0><<<dim3(4, 512), 256, GEMM_SMEM_BYTES>>>(out);        // out projection
}